// round 5
// baseline (speedup 1.0000x reference)
#include <cuda_runtime.h>
#include <cstdint>

#define Tz 512
#define Bz 32
#define Iz 256
#define Hz 512
#define Gz 2048          // 4*H
#define TB (Tz*Bz)       // 16384

// -------- scratch (device globals; no runtime allocation) --------
__device__ float g_xt[(size_t)TB * Iz];        // x transposed to [T,B,I]
__device__ float g_xg0[(size_t)TB * Gz];       // fwd-dir input-gate projections
__device__ float g_xg1[(size_t)TB * Gz];       // bwd-dir input-gate projections
__device__ float g_y0[(size_t)TB * 2 * Hz];    // layer-0 output [T,B,2H]
__device__ float g_hbuf[2][2][Hz * Bz];        // [dir][parity][u*32+b]  (k-major!)
__device__ float g_cbuf[2][Bz * Hz];           // [dir][b*H+u]
__device__ unsigned g_barcnt[2];               // per-direction arrival counters

__device__ __forceinline__ float sigf(float x) { return 1.f / (1.f + __expf(-x)); }
__device__ __forceinline__ float tanhf_(float x) { return 2.f / (1.f + __expf(-2.f * x)) - 1.f; }

__device__ __forceinline__ uint32_t f2tf32(float f) {
    uint32_t r;
    asm("cvt.rna.tf32.f32 %0, %1;" : "=r"(r) : "f"(f));
    return r;
}

// packed fp32 pair FMA (Blackwell sm_100+ base PTX; exact fp32)
__device__ __forceinline__ unsigned long long fma2(unsigned long long a,
                                                   unsigned long long b,
                                                   unsigned long long c) {
    unsigned long long d;
    asm("fma.rn.f32x2 %0, %1, %2, %3;" : "=l"(d) : "l"(a), "l"(b), "l"(c));
    return d;
}

// mma.sync tf32 m16n8k8 (portable sm_80+ path; runs on Blackwell tensor pipe)
__device__ __forceinline__ void mma_tf32(float* c, const uint32_t* a,
                                         uint32_t b0, uint32_t b1) {
    asm volatile(
        "mma.sync.aligned.m16n8k8.row.col.f32.tf32.tf32.f32 "
        "{%0,%1,%2,%3}, {%4,%5,%6,%7}, {%8,%9}, {%0,%1,%2,%3};"
        : "+f"(c[0]), "+f"(c[1]), "+f"(c[2]), "+f"(c[3])
        : "r"(a[0]), "r"(a[1]), "r"(a[2]), "r"(a[3]), "r"(b0), "r"(b1));
}

// -------- transpose x [B,I,T] -> xt [T,B,I] --------
__global__ void transpose_x(const float* __restrict__ x) {
    __shared__ float tile[32][33];
    int b = blockIdx.z, i0 = blockIdx.y * 32, t0 = blockIdx.x * 32;
    int tx = threadIdx.x, ty = threadIdx.y;
#pragma unroll
    for (int r = ty; r < 32; r += 8)
        tile[r][tx] = x[(size_t)b * Iz * Tz + (size_t)(i0 + r) * Tz + t0 + tx];
    __syncthreads();
#pragma unroll
    for (int r = ty; r < 32; r += 8)
        g_xt[(size_t)(t0 + r) * Bz * Iz + (size_t)b * Iz + i0 + tx] = tile[tx][r];
}

// ======== tf32 mma.sync GEMM: C[M,Gz] = A[M,K] @ W[Gz,K]^T + bi + bh ========
__global__ __launch_bounds__(256) void gemm_xg_mma(
    const float* __restrict__ A, const float* __restrict__ W,
    const float* __restrict__ bi, const float* __restrict__ bh,
    float* __restrict__ C, int K)
{
    __shared__ uint32_t As[128 * 36];
    __shared__ uint32_t Bs[128 * 36];

    int tid = threadIdx.x;
    int wid = tid >> 5, lane = tid & 31;
    int gid = lane >> 2, tig = lane & 3;
    int n0 = blockIdx.x * 128, m0 = blockIdx.y * 128;
    int mwarp = (wid >> 1) * 32;
    int nwarp = (wid & 1) * 64;

    float c[2][8][4];
#pragma unroll
    for (int mt = 0; mt < 2; mt++)
#pragma unroll
        for (int nt = 0; nt < 8; nt++)
#pragma unroll
            for (int q = 0; q < 4; q++) c[mt][nt][q] = 0.f;

    for (int k0 = 0; k0 < K; k0 += 32) {
#pragma unroll
        for (int j = 0; j < 4; j++) {
            int i = tid + j * 256;
            int row = i >> 3, q = i & 7;
            float4 v = *(const float4*)&A[(size_t)(m0 + row) * K + k0 + q * 4];
            uint4 t;
            t.x = f2tf32(v.x); t.y = f2tf32(v.y); t.z = f2tf32(v.z); t.w = f2tf32(v.w);
            *(uint4*)&As[row * 36 + q * 4] = t;
        }
#pragma unroll
        for (int j = 0; j < 4; j++) {
            int i = tid + j * 256;
            int row = i >> 3, q = i & 7;
            float4 v = *(const float4*)&W[(size_t)(n0 + row) * K + k0 + q * 4];
            uint4 t;
            t.x = f2tf32(v.x); t.y = f2tf32(v.y); t.z = f2tf32(v.z); t.w = f2tf32(v.w);
            *(uint4*)&Bs[row * 36 + q * 4] = t;
        }
        __syncthreads();

#pragma unroll
        for (int kk = 0; kk < 32; kk += 8) {
            uint32_t a[2][4];
#pragma unroll
            for (int mt = 0; mt < 2; mt++) {
                int mrow = mwarp + mt * 16;
                a[mt][0] = As[(mrow + gid)     * 36 + kk + tig];
                a[mt][1] = As[(mrow + gid + 8) * 36 + kk + tig];
                a[mt][2] = As[(mrow + gid)     * 36 + kk + tig + 4];
                a[mt][3] = As[(mrow + gid + 8) * 36 + kk + tig + 4];
            }
#pragma unroll
            for (int nt = 0; nt < 8; nt++) {
                uint32_t b0 = Bs[(nwarp + nt * 8 + gid) * 36 + kk + tig];
                uint32_t b1 = Bs[(nwarp + nt * 8 + gid) * 36 + kk + tig + 4];
                mma_tf32(c[0][nt], a[0], b0, b1);
                mma_tf32(c[1][nt], a[1], b0, b1);
            }
        }
        __syncthreads();
    }

#pragma unroll
    for (int mt = 0; mt < 2; mt++) {
        int m = m0 + mwarp + mt * 16 + gid;
#pragma unroll
        for (int nt = 0; nt < 8; nt++) {
            int n = n0 + nwarp + nt * 8 + 2 * tig;
            float bs0 = bi[n] + bh[n];
            float bs1 = bi[n + 1] + bh[n + 1];
            float2 o0 = {c[mt][nt][0] + bs0, c[mt][nt][1] + bs1};
            float2 o1 = {c[mt][nt][2] + bs0, c[mt][nt][3] + bs1};
            *(float2*)&C[(size_t)m * Gz + n] = o0;
            *(float2*)&C[(size_t)(m + 8) * Gz + n] = o1;
        }
    }
}

// -------- grid barrier (per-direction, monotonic counter) --------
__device__ __forceinline__ void bar_sync(unsigned* cnt, unsigned target) {
    __syncthreads();
    if (threadIdx.x == 0) {
        __threadfence();
        atomicAdd(cnt, 1u);
        unsigned v;
        do {
            asm volatile("ld.acquire.gpu.u32 %0, [%1];" : "=r"(v) : "l"(cnt) : "memory");
        } while (v < target);
    }
    __syncthreads();
}

__global__ void reset_bar() {
    if (threadIdx.x < 2) g_barcnt[threadIdx.x] = 0;
}

// -------- persistent bidirectional LSTM recurrence (one launch = 512 steps) --------
// W_hh in SMEM DUPLICATED per column pair: w_s[k][2c]=w_s[k][2c+1]=W[c][k]
// so the inner loop is pure {2x LDS.128 + 4x FFMA2} per k.
#define SM_W  0                       // [512][64] floats (duplicated cols) = 32768
#define SM_H  32768                   // [512][32] floats = 16384
#define SM_G  49152                   // [32][33]
#define REC_SMEM_FLOATS (32768 + 16384 + 32 * 33)
#define REC_SMEM_BYTES  (REC_SMEM_FLOATS * 4)

__global__ __launch_bounds__(128) void lstm_rec(
    const float* __restrict__ Wf, const float* __restrict__ Wb,
    float* __restrict__ outbuf, int st_t, int st_b)
{
    extern __shared__ float sm[];
    float* w_s = sm + SM_W;     // [512 k][64] duplicated col pairs
    float* h_s = sm + SM_H;     // [512 k][32 b]
    float* g_s = sm + SM_G;     // [32 b][33]

    int dir = blockIdx.x & 1;
    int cb = blockIdx.x >> 1;
    int u0 = cb * 8;
    const float* W = dir ? Wb : Wf;
    const float* xg = dir ? g_xg1 : g_xg0;
    unsigned* cnt = &g_barcnt[dir];
    int tid = threadIdx.x;

    // ---- load this CTA's 32 W_hh rows into SMEM, duplicated (once) ----
    {
        int c = tid >> 2, kq = tid & 3;
        const float* wrow = W + (size_t)((c >> 3) * Hz + u0 + (c & 7)) * Hz;
#pragma unroll 4
        for (int p = 0; p < 32; p++) {
            int k = p * 16 + kq * 4;
            float4 v = *(const float4*)&wrow[k];
            w_s[(k + 0) * 64 + 2 * c] = v.x;  w_s[(k + 0) * 64 + 2 * c + 1] = v.x;
            w_s[(k + 1) * 64 + 2 * c] = v.y;  w_s[(k + 1) * 64 + 2 * c + 1] = v.y;
            w_s[(k + 2) * 64 + 2 * c] = v.z;  w_s[(k + 2) * 64 + 2 * c + 1] = v.z;
            w_s[(k + 3) * 64 + 2 * c] = v.w;  w_s[(k + 3) * 64 + 2 * c + 1] = v.w;
        }
    }

    {
        float* hz = g_hbuf[dir][0];
        hz[u0 * 32 + tid * 2 + 0] = 0.f;
        hz[u0 * 32 + tid * 2 + 1] = 0.f;
    }
    float creg[2] = {0.f, 0.f};

    bar_sync(cnt, 64u);

    int b0 = (tid >> 4) * 4;       // batch group of 4
    int c0 = (tid & 15) * 2;       // col pair
    int wq = (tid & 15) * 4;       // float index of duplicated pair in w_s row

    for (int s = 0; s < Tz; s++) {
        int rb = s & 1;
        int wb = rb ^ 1;
        int t = dir ? (Tz - 1 - s) : s;
        const float* hp = g_hbuf[dir][rb];

        for (int i = tid; i < 4096; i += 128) {
            float4 v = __ldcg((const float4*)hp + i);
            *(float4*)&h_s[i * 4] = v;
        }
        __syncthreads();

        // acc2[pair][col]: pair 0 = batches (b0,b0+1), pair 1 = (b0+2,b0+3)
        unsigned long long acc2[2][2] = {{0ull, 0ull}, {0ull, 0ull}};
#pragma unroll 8
        for (int k = 0; k < Hz; k++) {
            ulonglong2 ha = *(const ulonglong2*)&h_s[k * 32 + b0];
            ulonglong2 wv = *(const ulonglong2*)&w_s[k * 64 + wq];
            acc2[0][0] = fma2(ha.x, wv.x, acc2[0][0]);
            acc2[0][1] = fma2(ha.x, wv.y, acc2[0][1]);
            acc2[1][0] = fma2(ha.y, wv.x, acc2[1][0]);
            acc2[1][1] = fma2(ha.y, wv.y, acc2[1][1]);
        }

#pragma unroll
        for (int i = 0; i < 2; i++)
#pragma unroll
            for (int j = 0; j < 2; j++) {
                float2 f = *(float2*)&acc2[i][j];
                g_s[(b0 + 2 * i + 0) * 33 + c0 + j] = f.x;
                g_s[(b0 + 2 * i + 1) * 33 + c0 + j] = f.y;
            }
        __syncthreads();

        float* hnew = g_hbuf[dir][wb];
        const float* xgt = xg + (size_t)t * Bz * Gz;
#pragma unroll
        for (int q = 0; q < 2; q++) {
            int pp = tid * 2 + q;
            int b = pp >> 3, ul = pp & 7;
            int u = u0 + ul;
            const float* xr = xgt + (size_t)b * Gz + u;
            float gi = g_s[b * 33 + 0  + ul] + xr[0 * Hz];
            float gf = g_s[b * 33 + 8  + ul] + xr[1 * Hz];
            float gg = g_s[b * 33 + 16 + ul] + xr[2 * Hz];
            float go = g_s[b * 33 + 24 + ul] + xr[3 * Hz];
            float iv = sigf(gi), fv = sigf(gf), gv = tanhf_(gg), ov = sigf(go);
            float cn = fv * creg[q] + iv * gv;
            float hn = ov * tanhf_(cn);
            creg[q] = cn;
            hnew[u * 32 + b] = hn;
            outbuf[(size_t)t * st_t + (size_t)b * st_b + dir * Hz + u] = hn;
        }

        bar_sync(cnt, 64u * (unsigned)(s + 2));
    }

#pragma unroll
    for (int q = 0; q < 2; q++) {
        int pp = tid * 2 + q;
        int b = pp >> 3, u = u0 + (pp & 7);
        g_cbuf[dir][b * Hz + u] = creg[q];
    }
}

// -------- copy final h/c into h_n / c_n sections of d_out --------
__global__ void copy_state(float* __restrict__ dout, int layer) {
    int idx = blockIdx.x * 256 + threadIdx.x;   // 0..32767
    int d = idx >> 14;
    int r = idx & 16383;           // r = b*512 + u
    int b = r >> 9, u = r & 511;
    const size_t OUT = (size_t)Bz * Tz * 2 * Hz;
    dout[OUT + (size_t)(2 * layer + d) * (Bz * Hz) + r] = g_hbuf[d][0][u * 32 + b];
    dout[OUT + 4 * (size_t)(Bz * Hz) + (size_t)(2 * layer + d) * (Bz * Hz) + r] = g_cbuf[d][r];
}

extern "C" void kernel_launch(void* const* d_in, const int* in_sizes, int n_in,
                              void* d_out, int out_size)
{
    const float* x        = (const float*)d_in[0];
    const float* w_ih_l0  = (const float*)d_in[1];
    const float* w_hh_l0  = (const float*)d_in[2];
    const float* b_ih_l0  = (const float*)d_in[3];
    const float* b_hh_l0  = (const float*)d_in[4];
    const float* w_ih_l0r = (const float*)d_in[5];
    const float* w_hh_l0r = (const float*)d_in[6];
    const float* b_ih_l0r = (const float*)d_in[7];
    const float* b_hh_l0r = (const float*)d_in[8];
    const float* w_ih_l1  = (const float*)d_in[9];
    const float* w_hh_l1  = (const float*)d_in[10];
    const float* b_ih_l1  = (const float*)d_in[11];
    const float* b_hh_l1  = (const float*)d_in[12];
    const float* w_ih_l1r = (const float*)d_in[13];
    const float* w_hh_l1r = (const float*)d_in[14];
    const float* b_ih_l1r = (const float*)d_in[15];
    const float* b_hh_l1r = (const float*)d_in[16];
    float* out = (float*)d_out;

    void* p;
    float *xt, *y0, *xg0, *xg1;
    cudaGetSymbolAddress(&p, g_xt);   xt  = (float*)p;
    cudaGetSymbolAddress(&p, g_y0);   y0  = (float*)p;
    cudaGetSymbolAddress(&p, g_xg0);  xg0 = (float*)p;
    cudaGetSymbolAddress(&p, g_xg1);  xg1 = (float*)p;

    cudaFuncSetAttribute(lstm_rec, cudaFuncAttributeMaxDynamicSharedMemorySize,
                         REC_SMEM_BYTES);

    // x [B,I,T] -> xt [T,B,I]
    transpose_x<<<dim3(Tz / 32, Iz / 32, Bz), dim3(32, 8)>>>(x);

    dim3 gg(Gz / 128, TB / 128);   // (16, 128)

    // ---- layer 0 ----
    gemm_xg_mma<<<gg, 256>>>(xt, w_ih_l0,  b_ih_l0,  b_hh_l0,  xg0, Iz);
    gemm_xg_mma<<<gg, 256>>>(xt, w_ih_l0r, b_ih_l0r, b_hh_l0r, xg1, Iz);
    reset_bar<<<1, 32>>>();
    lstm_rec<<<128, 128, REC_SMEM_BYTES>>>(w_hh_l0, w_hh_l0r, y0,
                                           Bz * 2 * Hz, 2 * Hz);
    copy_state<<<128, 256>>>(out, 0);

    // ---- layer 1 ----
    gemm_xg_mma<<<gg, 256>>>(y0, w_ih_l1,  b_ih_l1,  b_hh_l1,  xg0, 2 * Hz);
    gemm_xg_mma<<<gg, 256>>>(y0, w_ih_l1r, b_ih_l1r, b_hh_l1r, xg1, 2 * Hz);
    reset_bar<<<1, 32>>>();
    lstm_rec<<<128, 128, REC_SMEM_BYTES>>>(w_hh_l1, w_hh_l1r, out,
                                           2 * Hz, Tz * 2 * Hz);
    copy_state<<<128, 256>>>(out, 1);
}

// round 6
// speedup vs baseline: 2.0640x; 2.0640x over previous
#include <cuda_runtime.h>
#include <cuda_bf16.h>
#include <cstdint>

#define Tz 512
#define Bz 32
#define Iz 256
#define Hz 512
#define Gz 2048          // 4*H
#define TB (Tz*Bz)       // 16384

// -------- scratch (device globals; no runtime allocation) --------
__device__ float g_xt[(size_t)TB * Iz];        // x transposed to [T,B,I]
__device__ float g_xg0[(size_t)TB * Gz];       // fwd-dir input-gate projections
__device__ float g_xg1[(size_t)TB * Gz];       // bwd-dir input-gate projections
__device__ float g_y0[(size_t)TB * 2 * Hz];    // layer-0 output [T,B,2H]
__device__ unsigned g_hbuf[2][2][Bz * Hz];     // [dir][parity][b*512+u] packed (bf16hi<<16)|bf16lo
__device__ float g_cbuf[2][Bz * Hz];           // [dir][b*H+u]
__device__ unsigned g_barcnt[2];               // per-direction arrival counters

__device__ __forceinline__ float sigf(float x) { return 1.f / (1.f + __expf(-x)); }
__device__ __forceinline__ float tanhf_(float x) { return 2.f / (1.f + __expf(-2.f * x)) - 1.f; }

__device__ __forceinline__ uint32_t f2tf32(float f) {
    uint32_t r;
    asm("cvt.rna.tf32.f32 %0, %1;" : "=r"(r) : "f"(f));
    return r;
}

__device__ __forceinline__ uint32_t smem_u32(const void* p) {
    uint32_t a;
    asm("{ .reg .u64 t; cvta.to.shared.u64 t, %1; cvt.u32.u64 %0, t; }" : "=r"(a) : "l"(p));
    return a;
}

// mma.sync tf32 m16n8k8 (input GEMMs)
__device__ __forceinline__ void mma_tf32(float* c, const uint32_t* a,
                                         uint32_t b0, uint32_t b1) {
    asm volatile(
        "mma.sync.aligned.m16n8k8.row.col.f32.tf32.tf32.f32 "
        "{%0,%1,%2,%3}, {%4,%5,%6,%7}, {%8,%9}, {%0,%1,%2,%3};"
        : "+f"(c[0]), "+f"(c[1]), "+f"(c[2]), "+f"(c[3])
        : "r"(a[0]), "r"(a[1]), "r"(a[2]), "r"(a[3]), "r"(b0), "r"(b1));
}

// mma.sync bf16 m16n8k16 (recurrence)
__device__ __forceinline__ void mma_bf16(float* c, const uint32_t* a,
                                         uint32_t b0, uint32_t b1) {
    asm volatile(
        "mma.sync.aligned.m16n8k16.row.col.f32.bf16.bf16.f32 "
        "{%0,%1,%2,%3}, {%4,%5,%6,%7}, {%8,%9}, {%0,%1,%2,%3};"
        : "+f"(c[0]), "+f"(c[1]), "+f"(c[2]), "+f"(c[3])
        : "r"(a[0]), "r"(a[1]), "r"(a[2]), "r"(a[3]), "r"(b0), "r"(b1));
}

#define LDSM4(d0, d1, d2, d3, a)                                                \
    asm volatile("ldmatrix.sync.aligned.m8n8.x4.shared.b16 {%0,%1,%2,%3}, [%4];"\
                 : "=r"(d0), "=r"(d1), "=r"(d2), "=r"(d3) : "r"(a))
#define LDSM2(d0, d1, a)                                                        \
    asm volatile("ldmatrix.sync.aligned.m8n8.x2.shared.b16 {%0,%1}, [%2];"      \
                 : "=r"(d0), "=r"(d1) : "r"(a))

// -------- transpose x [B,I,T] -> xt [T,B,I] --------
__global__ void transpose_x(const float* __restrict__ x) {
    __shared__ float tile[32][33];
    int b = blockIdx.z, i0 = blockIdx.y * 32, t0 = blockIdx.x * 32;
    int tx = threadIdx.x, ty = threadIdx.y;
#pragma unroll
    for (int r = ty; r < 32; r += 8)
        tile[r][tx] = x[(size_t)b * Iz * Tz + (size_t)(i0 + r) * Tz + t0 + tx];
    __syncthreads();
#pragma unroll
    for (int r = ty; r < 32; r += 8)
        g_xt[(size_t)(t0 + r) * Bz * Iz + (size_t)b * Iz + i0 + tx] = tile[tx][r];
}

// ======== tf32 mma.sync GEMM: C[M,Gz] = A[M,K] @ W[Gz,K]^T + bi + bh ========
__global__ __launch_bounds__(256) void gemm_xg_mma(
    const float* __restrict__ A, const float* __restrict__ W,
    const float* __restrict__ bi, const float* __restrict__ bh,
    float* __restrict__ C, int K)
{
    __shared__ uint32_t As[128 * 36];
    __shared__ uint32_t Bs[128 * 36];

    int tid = threadIdx.x;
    int wid = tid >> 5, lane = tid & 31;
    int gid = lane >> 2, tig = lane & 3;
    int n0 = blockIdx.x * 128, m0 = blockIdx.y * 128;
    int mwarp = (wid >> 1) * 32;
    int nwarp = (wid & 1) * 64;

    float c[2][8][4];
#pragma unroll
    for (int mt = 0; mt < 2; mt++)
#pragma unroll
        for (int nt = 0; nt < 8; nt++)
#pragma unroll
            for (int q = 0; q < 4; q++) c[mt][nt][q] = 0.f;

    for (int k0 = 0; k0 < K; k0 += 32) {
#pragma unroll
        for (int j = 0; j < 4; j++) {
            int i = tid + j * 256;
            int row = i >> 3, q = i & 7;
            float4 v = *(const float4*)&A[(size_t)(m0 + row) * K + k0 + q * 4];
            uint4 t;
            t.x = f2tf32(v.x); t.y = f2tf32(v.y); t.z = f2tf32(v.z); t.w = f2tf32(v.w);
            *(uint4*)&As[row * 36 + q * 4] = t;
        }
#pragma unroll
        for (int j = 0; j < 4; j++) {
            int i = tid + j * 256;
            int row = i >> 3, q = i & 7;
            float4 v = *(const float4*)&W[(size_t)(n0 + row) * K + k0 + q * 4];
            uint4 t;
            t.x = f2tf32(v.x); t.y = f2tf32(v.y); t.z = f2tf32(v.z); t.w = f2tf32(v.w);
            *(uint4*)&Bs[row * 36 + q * 4] = t;
        }
        __syncthreads();

#pragma unroll
        for (int kk = 0; kk < 32; kk += 8) {
            uint32_t a[2][4];
#pragma unroll
            for (int mt = 0; mt < 2; mt++) {
                int mrow = mwarp + mt * 16;
                a[mt][0] = As[(mrow + gid)     * 36 + kk + tig];
                a[mt][1] = As[(mrow + gid + 8) * 36 + kk + tig];
                a[mt][2] = As[(mrow + gid)     * 36 + kk + tig + 4];
                a[mt][3] = As[(mrow + gid + 8) * 36 + kk + tig + 4];
            }
#pragma unroll
            for (int nt = 0; nt < 8; nt++) {
                uint32_t b0 = Bs[(nwarp + nt * 8 + gid) * 36 + kk + tig];
                uint32_t b1 = Bs[(nwarp + nt * 8 + gid) * 36 + kk + tig + 4];
                mma_tf32(c[0][nt], a[0], b0, b1);
                mma_tf32(c[1][nt], a[1], b0, b1);
            }
        }
        __syncthreads();
    }

#pragma unroll
    for (int mt = 0; mt < 2; mt++) {
        int m = m0 + mwarp + mt * 16 + gid;
#pragma unroll
        for (int nt = 0; nt < 8; nt++) {
            int n = n0 + nwarp + nt * 8 + 2 * tig;
            float bs0 = bi[n] + bh[n];
            float bs1 = bi[n + 1] + bh[n + 1];
            float2 o0 = {c[mt][nt][0] + bs0, c[mt][nt][1] + bs1};
            float2 o1 = {c[mt][nt][2] + bs0, c[mt][nt][3] + bs1};
            *(float2*)&C[(size_t)m * Gz + n] = o0;
            *(float2*)&C[(size_t)(m + 8) * Gz + n] = o1;
        }
    }
}

// -------- grid barrier (per-direction, monotonic counter) --------
__device__ __forceinline__ void bar_sync(unsigned* cnt, unsigned target) {
    __syncthreads();
    if (threadIdx.x == 0) {
        __threadfence();
        atomicAdd(cnt, 1u);
        unsigned v;
        do {
            asm volatile("ld.acquire.gpu.u32 %0, [%1];" : "=r"(v) : "l"(cnt) : "memory");
        } while (v < target);
    }
    __syncthreads();
}

__global__ void reset_bar() {
    if (threadIdx.x < 2) g_barcnt[threadIdx.x] = 0;
}

// ======== persistent bidirectional LSTM recurrence — bf16-split tensor path ========
// 128 CTAs (dir = bx&1, cb = bx>>1), 128 threads (4 warps = 4 gates x 8 units).
// W split (bf16 hi/lo) resident in SMEM planes [32 cols][520 k]; h restaged per
// step into [32 b][520 k] hi/lo planes; 3x mma.m16n8k16.bf16 per tile ~ fp32.
#define RSTRIDE_B 1040                 // 520 bf16 per row
#define RSM_WHI 0
#define RSM_WLO 33280
#define RSM_AHI 66560
#define RSM_ALO 99840
#define RSM_GS  133120                 // float[32][34]
#define REC_SMEM_BYTES (133120 + 32 * 34 * 4)

__global__ __launch_bounds__(128) void lstm_rec(
    const float* __restrict__ Wf, const float* __restrict__ Wb,
    float* __restrict__ outbuf, int st_t, int st_b)
{
    extern __shared__ char smr[];
    uint32_t sbase = smem_u32(smr);
    float* gs = (float*)(smr + RSM_GS);

    int dir = blockIdx.x & 1;
    int cb = blockIdx.x >> 1;
    int u0 = cb * 8;
    const float* W = dir ? Wb : Wf;
    const float* xg = dir ? g_xg1 : g_xg0;
    unsigned* cnt = &g_barcnt[dir];
    int tid = threadIdx.x;
    int wid = tid >> 5, l = tid & 31;
    int gid = l >> 2, tig = l & 3;

    // ---- split this CTA's 32 W_hh rows into bf16 hi/lo planes (once) ----
    {
        int c = tid >> 2, kq = tid & 3;
        const float* wrow = W + (size_t)((c >> 3) * Hz + u0 + (c & 7)) * Hz;
        __nv_bfloat16* whi = (__nv_bfloat16*)(smr + RSM_WHI);
        __nv_bfloat16* wlo = (__nv_bfloat16*)(smr + RSM_WLO);
#pragma unroll 4
        for (int p = 0; p < 32; p++) {
            int k = p * 16 + kq * 4;
            float4 v = *(const float4*)&wrow[k];
            float vv[4] = {v.x, v.y, v.z, v.w};
#pragma unroll
            for (int j = 0; j < 4; j++) {
                __nv_bfloat16 hb = __float2bfloat16(vv[j]);
                whi[c * 520 + k + j] = hb;
                wlo[c * 520 + k + j] = __float2bfloat16(vv[j] - __bfloat162float(hb));
            }
        }
    }

    // ---- zero h parity 0 (each CTA zeros its 1/64 chunk of its dir) ----
    {
        unsigned* hz = g_hbuf[dir][0];
        hz[cb * 256 + tid * 2 + 0] = 0u;
        hz[cb * 256 + tid * 2 + 1] = 0u;
    }
    float creg[2] = {0.f, 0.f};

    bar_sync(cnt, 64u);

    // ldmatrix lane address bases
    int r_a = l & 15;
    uint32_t aoff = sbase + RSM_AHI + (uint32_t)r_a * RSTRIDE_B + (uint32_t)((l >> 4) * 16);
    uint32_t boff = sbase + RSM_WHI + (uint32_t)(wid * 8 + (l & 7)) * RSTRIDE_B
                  + (uint32_t)(((l >> 3) & 1) * 16);

    for (int s = 0; s < Tz; s++) {
        int rb = s & 1;
        int wb = rb ^ 1;
        int t = dir ? (Tz - 1 - s) : s;
        const unsigned* hp = g_hbuf[dir][rb];

        // prefetch this thread's xg gate values (hidden under staging + mma)
        float xv[2][4];
#pragma unroll
        for (int q = 0; q < 2; q++) {
            int pp = tid * 2 + q;
            int b = pp >> 3, ul = pp & 7;
            const float* xr = xg + (size_t)t * Bz * Gz + (size_t)b * Gz + u0 + ul;
            xv[q][0] = xr[0 * Hz]; xv[q][1] = xr[1 * Hz];
            xv[q][2] = xr[2 * Hz]; xv[q][3] = xr[3 * Hz];
        }

        // ---- stage h: packed global [b][u] -> bf16 hi/lo SMEM planes ----
#pragma unroll 4
        for (int j = 0; j < 32; j++) {
            uint4 w = __ldcg((const uint4*)(hp + j * 512 + tid * 4));
            uint32_t hi01 = __byte_perm(w.x, w.y, 0x7632);
            uint32_t hi23 = __byte_perm(w.z, w.w, 0x7632);
            uint32_t lo01 = __byte_perm(w.x, w.y, 0x5410);
            uint32_t lo23 = __byte_perm(w.z, w.w, 0x5410);
            uint2 hv = {hi01, hi23}, lv = {lo01, lo23};
            *(uint2*)(smr + RSM_AHI + j * RSTRIDE_B + tid * 8) = hv;
            *(uint2*)(smr + RSM_ALO + j * RSTRIDE_B + tid * 8) = lv;
        }
        __syncthreads();

        // ---- 32(b) x 8(cols of this warp's gate) x K=512, 3-mma bf16 split ----
        float c0[4] = {0.f, 0.f, 0.f, 0.f};
        float c1[4] = {0.f, 0.f, 0.f, 0.f};
#pragma unroll 8
        for (int kk = 0; kk < Hz; kk += 16) {
            uint32_t ko = kk * 2;
            uint32_t ah[8], al[8], bh[2], bl[2];
            LDSM4(ah[0], ah[1], ah[2], ah[3], aoff + ko);
            LDSM4(ah[4], ah[5], ah[6], ah[7], aoff + 16 * RSTRIDE_B + ko);
            LDSM4(al[0], al[1], al[2], al[3], aoff + 33280 + ko);
            LDSM4(al[4], al[5], al[6], al[7], aoff + 33280 + 16 * RSTRIDE_B + ko);
            LDSM2(bh[0], bh[1], boff + ko);
            LDSM2(bl[0], bl[1], boff + 33280 + ko);
            mma_bf16(c0, ah,     bh[0], bh[1]);
            mma_bf16(c1, ah + 4, bh[0], bh[1]);
            mma_bf16(c0, ah,     bl[0], bl[1]);
            mma_bf16(c1, ah + 4, bl[0], bl[1]);
            mma_bf16(c0, al,     bh[0], bh[1]);
            mma_bf16(c1, al + 4, bh[0], bh[1]);
        }

        // ---- scatter C fragments to gs[b][34] ----
        {
            int colw = wid * 8 + 2 * tig;
            float2 v;
            v.x = c0[0]; v.y = c0[1]; *(float2*)&gs[(gid)      * 34 + colw] = v;
            v.x = c0[2]; v.y = c0[3]; *(float2*)&gs[(gid + 8)  * 34 + colw] = v;
            v.x = c1[0]; v.y = c1[1]; *(float2*)&gs[(gid + 16) * 34 + colw] = v;
            v.x = c1[2]; v.y = c1[3]; *(float2*)&gs[(gid + 24) * 34 + colw] = v;
        }
        __syncthreads();

        // ---- gate nonlinearity + state update ----
        unsigned* hnew = g_hbuf[dir][wb];
#pragma unroll
        for (int q = 0; q < 2; q++) {
            int pp = tid * 2 + q;
            int b = pp >> 3, ul = pp & 7;
            int u = u0 + ul;
            float gi = gs[b * 34 + 0  + ul] + xv[q][0];
            float gf = gs[b * 34 + 8  + ul] + xv[q][1];
            float gg = gs[b * 34 + 16 + ul] + xv[q][2];
            float go = gs[b * 34 + 24 + ul] + xv[q][3];
            float iv = sigf(gi), fv = sigf(gf), gv = tanhf_(gg), ov = sigf(go);
            float cn = fv * creg[q] + iv * gv;
            float hn = ov * tanhf_(cn);
            creg[q] = cn;
            __nv_bfloat16 hb = __float2bfloat16(hn);
            __nv_bfloat16 lb = __float2bfloat16(hn - __bfloat162float(hb));
            hnew[b * 512 + u] = ((unsigned)__bfloat16_as_ushort(hb) << 16)
                              | (unsigned)__bfloat16_as_ushort(lb);
            outbuf[(size_t)t * st_t + (size_t)b * st_b + dir * Hz + u] = hn;
        }

        bar_sync(cnt, 64u * (unsigned)(s + 2));
    }

#pragma unroll
    for (int q = 0; q < 2; q++) {
        int pp = tid * 2 + q;
        int b = pp >> 3, u = u0 + (pp & 7);
        g_cbuf[dir][b * Hz + u] = creg[q];
    }
}

// -------- copy final h/c into h_n / c_n sections of d_out --------
__global__ void copy_state(float* __restrict__ dout, int layer) {
    int idx = blockIdx.x * 256 + threadIdx.x;   // 0..32767
    int d = idx >> 14;
    int r = idx & 16383;           // r = b*512 + u
    const size_t OUT = (size_t)Bz * Tz * 2 * Hz;
    unsigned w = g_hbuf[d][0][r];
    float hv = __uint_as_float(w & 0xFFFF0000u) + __uint_as_float(w << 16);
    dout[OUT + (size_t)(2 * layer + d) * (Bz * Hz) + r] = hv;
    dout[OUT + 4 * (size_t)(Bz * Hz) + (size_t)(2 * layer + d) * (Bz * Hz) + r] = g_cbuf[d][r];
}

extern "C" void kernel_launch(void* const* d_in, const int* in_sizes, int n_in,
                              void* d_out, int out_size)
{
    const float* x        = (const float*)d_in[0];
    const float* w_ih_l0  = (const float*)d_in[1];
    const float* w_hh_l0  = (const float*)d_in[2];
    const float* b_ih_l0  = (const float*)d_in[3];
    const float* b_hh_l0  = (const float*)d_in[4];
    const float* w_ih_l0r = (const float*)d_in[5];
    const float* w_hh_l0r = (const float*)d_in[6];
    const float* b_ih_l0r = (const float*)d_in[7];
    const float* b_hh_l0r = (const float*)d_in[8];
    const float* w_ih_l1  = (const float*)d_in[9];
    const float* w_hh_l1  = (const float*)d_in[10];
    const float* b_ih_l1  = (const float*)d_in[11];
    const float* b_hh_l1  = (const float*)d_in[12];
    const float* w_ih_l1r = (const float*)d_in[13];
    const float* w_hh_l1r = (const float*)d_in[14];
    const float* b_ih_l1r = (const float*)d_in[15];
    const float* b_hh_l1r = (const float*)d_in[16];
    float* out = (float*)d_out;

    void* p;
    float *xt, *y0, *xg0, *xg1;
    cudaGetSymbolAddress(&p, g_xt);   xt  = (float*)p;
    cudaGetSymbolAddress(&p, g_y0);   y0  = (float*)p;
    cudaGetSymbolAddress(&p, g_xg0);  xg0 = (float*)p;
    cudaGetSymbolAddress(&p, g_xg1);  xg1 = (float*)p;

    cudaFuncSetAttribute(lstm_rec, cudaFuncAttributeMaxDynamicSharedMemorySize,
                         REC_SMEM_BYTES);

    // x [B,I,T] -> xt [T,B,I]
    transpose_x<<<dim3(Tz / 32, Iz / 32, Bz), dim3(32, 8)>>>(x);

    dim3 gg(Gz / 128, TB / 128);   // (16, 128)

    // ---- layer 0 ----
    gemm_xg_mma<<<gg, 256>>>(xt, w_ih_l0,  b_ih_l0,  b_hh_l0,  xg0, Iz);
    gemm_xg_mma<<<gg, 256>>>(xt, w_ih_l0r, b_ih_l0r, b_hh_l0r, xg1, Iz);
    reset_bar<<<1, 32>>>();
    lstm_rec<<<128, 128, REC_SMEM_BYTES>>>(w_hh_l0, w_hh_l0r, y0,
                                           Bz * 2 * Hz, 2 * Hz);
    copy_state<<<128, 256>>>(out, 0);

    // ---- layer 1 ----
    gemm_xg_mma<<<gg, 256>>>(y0, w_ih_l1,  b_ih_l1,  b_hh_l1,  xg0, 2 * Hz);
    gemm_xg_mma<<<gg, 256>>>(y0, w_ih_l1r, b_ih_l1r, b_hh_l1r, xg1, 2 * Hz);
    reset_bar<<<1, 32>>>();
    lstm_rec<<<128, 128, REC_SMEM_BYTES>>>(w_hh_l1, w_hh_l1r, out,
                                           2 * Hz, Tz * 2 * Hz);
    copy_state<<<128, 256>>>(out, 1);
}

// round 7
// speedup vs baseline: 3.1060x; 1.5048x over previous
#include <cuda_runtime.h>
#include <cuda_bf16.h>
#include <cstdint>

#define Tz 512
#define Bz 32
#define Iz 256
#define Hz 512
#define Gz 2048          // 4*H
#define TB (Tz*Bz)       // 16384

// -------- scratch (device globals; no runtime allocation) --------
__device__ float g_xt[(size_t)TB * Iz];        // x transposed to [T,B,I]
__device__ float g_xg0[(size_t)TB * Gz];       // fwd-dir input-gate projections
__device__ float g_xg1[(size_t)TB * Gz];       // bwd-dir input-gate projections
__device__ float g_y0[(size_t)TB * 2 * Hz];    // layer-0 output [T,B,2H]
__device__ unsigned short g_hhi[2][2][Bz * Hz]; // [dir][parity][b*512+u] bf16 hi
__device__ unsigned short g_hlo[2][2][Bz * Hz]; // [dir][parity][b*512+u] bf16 lo
__device__ float g_cbuf[2][Bz * Hz];           // [dir][b*H+u]
__device__ unsigned g_barcnt[2];               // per-direction arrival counters

__device__ __forceinline__ float sigf(float x) { return 1.f / (1.f + __expf(-x)); }
__device__ __forceinline__ float tanhf_(float x) { return 2.f / (1.f + __expf(-2.f * x)) - 1.f; }

__device__ __forceinline__ uint32_t f2tf32(float f) {
    uint32_t r;
    asm("cvt.rna.tf32.f32 %0, %1;" : "=r"(r) : "f"(f));
    return r;
}

__device__ __forceinline__ uint32_t smem_u32(const void* p) {
    uint32_t a;
    asm("{ .reg .u64 t; cvta.to.shared.u64 t, %1; cvt.u32.u64 %0, t; }" : "=r"(a) : "l"(p));
    return a;
}

// mma.sync tf32 m16n8k8 (input GEMMs)
__device__ __forceinline__ void mma_tf32(float* c, const uint32_t* a,
                                         uint32_t b0, uint32_t b1) {
    asm volatile(
        "mma.sync.aligned.m16n8k8.row.col.f32.tf32.tf32.f32 "
        "{%0,%1,%2,%3}, {%4,%5,%6,%7}, {%8,%9}, {%0,%1,%2,%3};"
        : "+f"(c[0]), "+f"(c[1]), "+f"(c[2]), "+f"(c[3])
        : "r"(a[0]), "r"(a[1]), "r"(a[2]), "r"(a[3]), "r"(b0), "r"(b1));
}

// mma.sync bf16 m16n8k16 (recurrence)
__device__ __forceinline__ void mma_bf16(float* c, const uint32_t* a,
                                         uint32_t b0, uint32_t b1) {
    asm volatile(
        "mma.sync.aligned.m16n8k16.row.col.f32.bf16.bf16.f32 "
        "{%0,%1,%2,%3}, {%4,%5,%6,%7}, {%8,%9}, {%0,%1,%2,%3};"
        : "+f"(c[0]), "+f"(c[1]), "+f"(c[2]), "+f"(c[3])
        : "r"(a[0]), "r"(a[1]), "r"(a[2]), "r"(a[3]), "r"(b0), "r"(b1));
}

#define LDSM4(d0, d1, d2, d3, a)                                                \
    asm volatile("ldmatrix.sync.aligned.m8n8.x4.shared.b16 {%0,%1,%2,%3}, [%4];"\
                 : "=r"(d0), "=r"(d1), "=r"(d2), "=r"(d3) : "r"(a))
#define LDSM2(d0, d1, a)                                                        \
    asm volatile("ldmatrix.sync.aligned.m8n8.x2.shared.b16 {%0,%1}, [%2];"      \
                 : "=r"(d0), "=r"(d1) : "r"(a))
#define CP16(dst, src)                                                          \
    asm volatile("cp.async.cg.shared.global [%0], [%1], 16;" :: "r"(dst), "l"(src))
#define CPCOMMIT() asm volatile("cp.async.commit_group;" ::: "memory")
#define CPWAIT()   asm volatile("cp.async.wait_group 0;" ::: "memory")

// -------- transpose x [B,I,T] -> xt [T,B,I] --------
__global__ void transpose_x(const float* __restrict__ x) {
    __shared__ float tile[32][33];
    int b = blockIdx.z, i0 = blockIdx.y * 32, t0 = blockIdx.x * 32;
    int tx = threadIdx.x, ty = threadIdx.y;
#pragma unroll
    for (int r = ty; r < 32; r += 8)
        tile[r][tx] = x[(size_t)b * Iz * Tz + (size_t)(i0 + r) * Tz + t0 + tx];
    __syncthreads();
#pragma unroll
    for (int r = ty; r < 32; r += 8)
        g_xt[(size_t)(t0 + r) * Bz * Iz + (size_t)b * Iz + i0 + tx] = tile[tx][r];
}

// ======== tf32 mma.sync GEMM: C[M,Gz] = A[M,K] @ W[Gz,K]^T + bi + bh ========
__global__ __launch_bounds__(256) void gemm_xg_mma(
    const float* __restrict__ A, const float* __restrict__ W,
    const float* __restrict__ bi, const float* __restrict__ bh,
    float* __restrict__ C, int K)
{
    __shared__ uint32_t As[128 * 36];
    __shared__ uint32_t Bs[128 * 36];

    int tid = threadIdx.x;
    int wid = tid >> 5, lane = tid & 31;
    int gid = lane >> 2, tig = lane & 3;
    int n0 = blockIdx.x * 128, m0 = blockIdx.y * 128;
    int mwarp = (wid >> 1) * 32;
    int nwarp = (wid & 1) * 64;

    float c[2][8][4];
#pragma unroll
    for (int mt = 0; mt < 2; mt++)
#pragma unroll
        for (int nt = 0; nt < 8; nt++)
#pragma unroll
            for (int q = 0; q < 4; q++) c[mt][nt][q] = 0.f;

    for (int k0 = 0; k0 < K; k0 += 32) {
#pragma unroll
        for (int j = 0; j < 4; j++) {
            int i = tid + j * 256;
            int row = i >> 3, q = i & 7;
            float4 v = *(const float4*)&A[(size_t)(m0 + row) * K + k0 + q * 4];
            uint4 t;
            t.x = f2tf32(v.x); t.y = f2tf32(v.y); t.z = f2tf32(v.z); t.w = f2tf32(v.w);
            *(uint4*)&As[row * 36 + q * 4] = t;
        }
#pragma unroll
        for (int j = 0; j < 4; j++) {
            int i = tid + j * 256;
            int row = i >> 3, q = i & 7;
            float4 v = *(const float4*)&W[(size_t)(n0 + row) * K + k0 + q * 4];
            uint4 t;
            t.x = f2tf32(v.x); t.y = f2tf32(v.y); t.z = f2tf32(v.z); t.w = f2tf32(v.w);
            *(uint4*)&Bs[row * 36 + q * 4] = t;
        }
        __syncthreads();

#pragma unroll
        for (int kk = 0; kk < 32; kk += 8) {
            uint32_t a[2][4];
#pragma unroll
            for (int mt = 0; mt < 2; mt++) {
                int mrow = mwarp + mt * 16;
                a[mt][0] = As[(mrow + gid)     * 36 + kk + tig];
                a[mt][1] = As[(mrow + gid + 8) * 36 + kk + tig];
                a[mt][2] = As[(mrow + gid)     * 36 + kk + tig + 4];
                a[mt][3] = As[(mrow + gid + 8) * 36 + kk + tig + 4];
            }
#pragma unroll
            for (int nt = 0; nt < 8; nt++) {
                uint32_t b0 = Bs[(nwarp + nt * 8 + gid) * 36 + kk + tig];
                uint32_t b1 = Bs[(nwarp + nt * 8 + gid) * 36 + kk + tig + 4];
                mma_tf32(c[0][nt], a[0], b0, b1);
                mma_tf32(c[1][nt], a[1], b0, b1);
            }
        }
        __syncthreads();
    }

#pragma unroll
    for (int mt = 0; mt < 2; mt++) {
        int m = m0 + mwarp + mt * 16 + gid;
#pragma unroll
        for (int nt = 0; nt < 8; nt++) {
            int n = n0 + nwarp + nt * 8 + 2 * tig;
            float bs0 = bi[n] + bh[n];
            float bs1 = bi[n + 1] + bh[n + 1];
            float2 o0 = {c[mt][nt][0] + bs0, c[mt][nt][1] + bs1};
            float2 o1 = {c[mt][nt][2] + bs0, c[mt][nt][3] + bs1};
            *(float2*)&C[(size_t)m * Gz + n] = o0;
            *(float2*)&C[(size_t)(m + 8) * Gz + n] = o1;
        }
    }
}

// -------- grid barrier (per-direction, monotonic counter) --------
__device__ __forceinline__ void bar_sync(unsigned* cnt, unsigned target) {
    __syncthreads();
    if (threadIdx.x == 0) {
        __threadfence();
        atomicAdd(cnt, 1u);
        unsigned v;
        do {
            asm volatile("ld.acquire.gpu.u32 %0, [%1];" : "=r"(v) : "l"(cnt) : "memory");
        } while (v < target);
    }
    __syncthreads();
}

__global__ void reset_bar() {
    if (threadIdx.x < 2) g_barcnt[threadIdx.x] = 0;
}

// ======== persistent recurrence — K-split bf16 tensor path ========
// 128 CTAs (dir = bx&1, cb = bx>>1 owns units u0..u0+7 -> 32 gate-cols), 4 warps.
// Warp w handles k-range [w*128,(w+1)*128) for ALL 32 cols; partials reduced in SMEM.
// h in global as bf16 hi/lo planes; staged via cp.async (no unpack).
#define RST 1040                      // smem row stride bytes (520 bf16)
#define RSM_WHI 0                     // [32 c][520]
#define RSM_WLO 33280
#define RSM_AHI 66560                 // [32 b][520]
#define RSM_ALO 99840
#define RSM_PS  133120                // float[4][32][36]
#define REC_SMEM_BYTES (133120 + 4 * 32 * 36 * 4)

__global__ __launch_bounds__(128) void lstm_rec(
    const float* __restrict__ Wf, const float* __restrict__ Wb,
    float* __restrict__ outbuf, int st_t, int st_b)
{
    extern __shared__ char smr[];
    uint32_t sbase = smem_u32(smr);

    int dir = blockIdx.x & 1;
    int cb = blockIdx.x >> 1;
    int u0 = cb * 8;
    const float* W = dir ? Wb : Wf;
    const float* xg = dir ? g_xg1 : g_xg0;
    unsigned* cnt = &g_barcnt[dir];
    int tid = threadIdx.x;
    int wid = tid >> 5, l = tid & 31;
    int gid = l >> 2, tig = l & 3;

    // ---- split this CTA's 32 W_hh rows into bf16 hi/lo SMEM planes (once) ----
    {
        int c = tid >> 2, kq = tid & 3;
        const float* wrow = W + (size_t)((c >> 3) * Hz + u0 + (c & 7)) * Hz;
        unsigned short* whi = (unsigned short*)(smr + RSM_WHI);
        unsigned short* wlo = (unsigned short*)(smr + RSM_WLO);
#pragma unroll 4
        for (int p = 0; p < 32; p++) {
            int k = p * 16 + kq * 4;
            float4 v = *(const float4*)&wrow[k];
            float vv[4] = {v.x, v.y, v.z, v.w};
#pragma unroll
            for (int j = 0; j < 4; j++) {
                __nv_bfloat16 hb = __float2bfloat16(vv[j]);
                whi[c * 520 + k + j] = __bfloat16_as_ushort(hb);
                wlo[c * 520 + k + j] = __bfloat16_as_ushort(
                    __float2bfloat16(vv[j] - __bfloat162float(hb)));
            }
        }
    }

    // ---- zero h parity-0 planes (this CTA's 1/64 slice) ----
    g_hhi[dir][0][cb * 256 + tid * 2 + 0] = 0;
    g_hhi[dir][0][cb * 256 + tid * 2 + 1] = 0;
    g_hlo[dir][0][cb * 256 + tid * 2 + 0] = 0;
    g_hlo[dir][0][cb * 256 + tid * 2 + 1] = 0;
    float creg[2] = {0.f, 0.f};

    bar_sync(cnt, 64u);

    // ldmatrix bases (k-offset per warp = wid*128 k = wid*256 bytes)
    uint32_t abase = sbase + RSM_AHI + (uint32_t)(l & 15) * RST
                   + (uint32_t)((l >> 4) * 16) + (uint32_t)wid * 256;
    uint32_t bbase = sbase + RSM_WHI + (uint32_t)(l & 7) * RST
                   + (uint32_t)(((l >> 3) & 1) * 16) + (uint32_t)wid * 256;
    float* ps = (float*)(smr + RSM_PS);

    for (int s = 0; s < Tz; s++) {
        int rb = s & 1;
        int wb = rb ^ 1;
        int t = dir ? (Tz - 1 - s) : s;

        // prefetch this thread's xg gate values
        float xv[2][4];
#pragma unroll
        for (int q = 0; q < 2; q++) {
            int pp = tid * 2 + q;
            int b = pp >> 3, ul = pp & 7;
            const float* xr = xg + (size_t)t * Bz * Gz + (size_t)b * Gz + u0 + ul;
            xv[q][0] = xr[0 * Hz]; xv[q][1] = xr[1 * Hz];
            xv[q][2] = xr[2 * Hz]; xv[q][3] = xr[3 * Hz];
        }

        // ---- stage h hi/lo planes via cp.async (16 chunks x 2 planes / thread) ----
        {
            const char* hhi = (const char*)g_hhi[dir][rb];
            const char* hlo = (const char*)g_hlo[dir][rb];
#pragma unroll
            for (int j = 0; j < 16; j++) {
                int i = tid + j * 128;
                int row = i >> 6, ch = (i & 63) * 16;
                CP16(sbase + RSM_AHI + row * RST + ch, hhi + row * 1024 + ch);
                CP16(sbase + RSM_ALO + row * RST + ch, hlo + row * 1024 + ch);
            }
            CPCOMMIT();
            CPWAIT();
        }
        __syncthreads();

        // ---- partial gates: 32b x 32cols over this warp's k128, 3-mma split ----
        float c[2][4][4];
#pragma unroll
        for (int mt = 0; mt < 2; mt++)
#pragma unroll
            for (int nt = 0; nt < 4; nt++)
#pragma unroll
                for (int q = 0; q < 4; q++) c[mt][nt][q] = 0.f;

#pragma unroll
        for (int ki = 0; ki < 8; ki++) {
            uint32_t ko = ki * 32;
            uint32_t ah[8], al[8];
            LDSM4(ah[0], ah[1], ah[2], ah[3], abase + ko);
            LDSM4(ah[4], ah[5], ah[6], ah[7], abase + 16 * RST + ko);
            LDSM4(al[0], al[1], al[2], al[3], abase + 33280 + ko);
            LDSM4(al[4], al[5], al[6], al[7], abase + 33280 + 16 * RST + ko);
#pragma unroll
            for (int nt = 0; nt < 4; nt++) {
                uint32_t bh0, bh1, bl0, bl1;
                LDSM2(bh0, bh1, bbase + nt * 8 * RST + ko);
                LDSM2(bl0, bl1, bbase + 33280 + nt * 8 * RST + ko);
                mma_bf16(c[0][nt], ah,     bh0, bh1);
                mma_bf16(c[1][nt], ah + 4, bh0, bh1);
                mma_bf16(c[0][nt], ah,     bl0, bl1);
                mma_bf16(c[1][nt], ah + 4, bl0, bl1);
                mma_bf16(c[0][nt], al,     bh0, bh1);
                mma_bf16(c[1][nt], al + 4, bh0, bh1);
            }
        }

        // ---- scatter partials to ps[wid][32][36] ----
        {
            float* pw = ps + wid * (32 * 36);
#pragma unroll
            for (int nt = 0; nt < 4; nt++) {
                int col = nt * 8 + 2 * tig;
                float2 v;
                v.x = c[0][nt][0]; v.y = c[0][nt][1];
                *(float2*)&pw[(gid)      * 36 + col] = v;
                v.x = c[0][nt][2]; v.y = c[0][nt][3];
                *(float2*)&pw[(gid + 8)  * 36 + col] = v;
                v.x = c[1][nt][0]; v.y = c[1][nt][1];
                *(float2*)&pw[(gid + 16) * 36 + col] = v;
                v.x = c[1][nt][2]; v.y = c[1][nt][3];
                *(float2*)&pw[(gid + 24) * 36 + col] = v;
            }
        }
        __syncthreads();

        // ---- reduce partials + gate nonlinearity + state update ----
        unsigned short* hnhi = g_hhi[dir][wb];
        unsigned short* hnlo = g_hlo[dir][wb];
#pragma unroll
        for (int q = 0; q < 2; q++) {
            int pp = tid * 2 + q;
            int b = pp >> 3, ul = pp & 7;
            int u = u0 + ul;
            float gv4[4];
#pragma unroll
            for (int g = 0; g < 4; g++) {
                int base = b * 36 + g * 8 + ul;
                gv4[g] = ps[base] + ps[base + 1152] + ps[base + 2304] + ps[base + 3456]
                       + xv[q][g];
            }
            float iv = sigf(gv4[0]), fv = sigf(gv4[1]);
            float gg = tanhf_(gv4[2]), ov = sigf(gv4[3]);
            float cn = fv * creg[q] + iv * gg;
            float hn = ov * tanhf_(cn);
            creg[q] = cn;
            __nv_bfloat16 hb = __float2bfloat16(hn);
            hnhi[b * 512 + u] = __bfloat16_as_ushort(hb);
            hnlo[b * 512 + u] = __bfloat16_as_ushort(
                __float2bfloat16(hn - __bfloat162float(hb)));
            outbuf[(size_t)t * st_t + (size_t)b * st_b + dir * Hz + u] = hn;
        }

        bar_sync(cnt, 64u * (unsigned)(s + 2));
    }

#pragma unroll
    for (int q = 0; q < 2; q++) {
        int pp = tid * 2 + q;
        int b = pp >> 3, u = u0 + (pp & 7);
        g_cbuf[dir][b * Hz + u] = creg[q];
    }
}

// -------- copy final h/c into h_n / c_n sections of d_out --------
__global__ void copy_state(float* __restrict__ dout, int layer) {
    int idx = blockIdx.x * 256 + threadIdx.x;   // 0..32767
    int d = idx >> 14;
    int r = idx & 16383;           // r = b*512 + u
    const size_t OUT = (size_t)Bz * Tz * 2 * Hz;
    float hv = __bfloat162float(__ushort_as_bfloat16(g_hhi[d][0][r]))
             + __bfloat162float(__ushort_as_bfloat16(g_hlo[d][0][r]));
    dout[OUT + (size_t)(2 * layer + d) * (Bz * Hz) + r] = hv;
    dout[OUT + 4 * (size_t)(Bz * Hz) + (size_t)(2 * layer + d) * (Bz * Hz) + r] = g_cbuf[d][r];
}

extern "C" void kernel_launch(void* const* d_in, const int* in_sizes, int n_in,
                              void* d_out, int out_size)
{
    const float* x        = (const float*)d_in[0];
    const float* w_ih_l0  = (const float*)d_in[1];
    const float* w_hh_l0  = (const float*)d_in[2];
    const float* b_ih_l0  = (const float*)d_in[3];
    const float* b_hh_l0  = (const float*)d_in[4];
    const float* w_ih_l0r = (const float*)d_in[5];
    const float* w_hh_l0r = (const float*)d_in[6];
    const float* b_ih_l0r = (const float*)d_in[7];
    const float* b_hh_l0r = (const float*)d_in[8];
    const float* w_ih_l1  = (const float*)d_in[9];
    const float* w_hh_l1  = (const float*)d_in[10];
    const float* b_ih_l1  = (const float*)d_in[11];
    const float* b_hh_l1  = (const float*)d_in[12];
    const float* w_ih_l1r = (const float*)d_in[13];
    const float* w_hh_l1r = (const float*)d_in[14];
    const float* b_ih_l1r = (const float*)d_in[15];
    const float* b_hh_l1r = (const float*)d_in[16];
    float* out = (float*)d_out;

    void* p;
    float *xt, *y0, *xg0, *xg1;
    cudaGetSymbolAddress(&p, g_xt);   xt  = (float*)p;
    cudaGetSymbolAddress(&p, g_y0);   y0  = (float*)p;
    cudaGetSymbolAddress(&p, g_xg0);  xg0 = (float*)p;
    cudaGetSymbolAddress(&p, g_xg1);  xg1 = (float*)p;

    cudaFuncSetAttribute(lstm_rec, cudaFuncAttributeMaxDynamicSharedMemorySize,
                         REC_SMEM_BYTES);

    // x [B,I,T] -> xt [T,B,I]
    transpose_x<<<dim3(Tz / 32, Iz / 32, Bz), dim3(32, 8)>>>(x);

    dim3 gg(Gz / 128, TB / 128);   // (16, 128)

    // ---- layer 0 ----
    gemm_xg_mma<<<gg, 256>>>(xt, w_ih_l0,  b_ih_l0,  b_hh_l0,  xg0, Iz);
    gemm_xg_mma<<<gg, 256>>>(xt, w_ih_l0r, b_ih_l0r, b_hh_l0r, xg1, Iz);
    reset_bar<<<1, 32>>>();
    lstm_rec<<<128, 128, REC_SMEM_BYTES>>>(w_hh_l0, w_hh_l0r, y0,
                                           Bz * 2 * Hz, 2 * Hz);
    copy_state<<<128, 256>>>(out, 0);

    // ---- layer 1 ----
    gemm_xg_mma<<<gg, 256>>>(y0, w_ih_l1,  b_ih_l1,  b_hh_l1,  xg0, 2 * Hz);
    gemm_xg_mma<<<gg, 256>>>(y0, w_ih_l1r, b_ih_l1r, b_hh_l1r, xg1, 2 * Hz);
    reset_bar<<<1, 32>>>();
    lstm_rec<<<128, 128, REC_SMEM_BYTES>>>(w_hh_l1, w_hh_l1r, out,
                                           2 * Hz, Tz * 2 * Hz);
    copy_state<<<128, 256>>>(out, 1);
}

// round 8
// speedup vs baseline: 3.3146x; 1.0671x over previous
#include <cuda_runtime.h>
#include <cuda_bf16.h>
#include <cstdint>

#define Tz 512
#define Bz 32
#define Iz 256
#define Hz 512
#define Gz 2048          // 4*H
#define TB (Tz*Bz)       // 16384

// -------- scratch (device globals; no runtime allocation) --------
__device__ float g_xt[(size_t)TB * Iz];        // x transposed to [T,B,I]
__device__ float g_xg0[(size_t)TB * Gz];       // fwd-dir input-gate projections
__device__ float g_xg1[(size_t)TB * Gz];       // bwd-dir input-gate projections
__device__ float g_y0[(size_t)TB * 2 * Hz];    // layer-0 output [T,B,2H]
__device__ unsigned short g_hhi[2][2][Bz * Hz]; // [dir][parity][b*512+u] bf16 hi
__device__ unsigned short g_hlo[2][2][Bz * Hz]; // [dir][parity][b*512+u] bf16 lo
__device__ float g_cbuf[2][Bz * Hz];           // [dir][b*H+u]
__device__ unsigned g_barcnt[2];               // per-direction arrival counters

__device__ __forceinline__ float sigf(float x) { return 1.f / (1.f + __expf(-x)); }
__device__ __forceinline__ float tanhf_(float x) { return 2.f / (1.f + __expf(-2.f * x)) - 1.f; }

__device__ __forceinline__ uint32_t f2tf32(float f) {
    uint32_t r;
    asm("cvt.rna.tf32.f32 %0, %1;" : "=r"(r) : "f"(f));
    return r;
}

__device__ __forceinline__ uint32_t smem_u32(const void* p) {
    uint32_t a;
    asm("{ .reg .u64 t; cvta.to.shared.u64 t, %1; cvt.u32.u64 %0, t; }" : "=r"(a) : "l"(p));
    return a;
}

// mma.sync tf32 m16n8k8 (input GEMMs)
__device__ __forceinline__ void mma_tf32(float* c, const uint32_t* a,
                                         uint32_t b0, uint32_t b1) {
    asm volatile(
        "mma.sync.aligned.m16n8k8.row.col.f32.tf32.tf32.f32 "
        "{%0,%1,%2,%3}, {%4,%5,%6,%7}, {%8,%9}, {%0,%1,%2,%3};"
        : "+f"(c[0]), "+f"(c[1]), "+f"(c[2]), "+f"(c[3])
        : "r"(a[0]), "r"(a[1]), "r"(a[2]), "r"(a[3]), "r"(b0), "r"(b1));
}

// mma.sync bf16 m16n8k16 (recurrence)
__device__ __forceinline__ void mma_bf16(float* c, const uint32_t* a,
                                         uint32_t b0, uint32_t b1) {
    asm volatile(
        "mma.sync.aligned.m16n8k16.row.col.f32.bf16.bf16.f32 "
        "{%0,%1,%2,%3}, {%4,%5,%6,%7}, {%8,%9}, {%0,%1,%2,%3};"
        : "+f"(c[0]), "+f"(c[1]), "+f"(c[2]), "+f"(c[3])
        : "r"(a[0]), "r"(a[1]), "r"(a[2]), "r"(a[3]), "r"(b0), "r"(b1));
}

#define LDSM4(d0, d1, d2, d3, a)                                                \
    asm volatile("ldmatrix.sync.aligned.m8n8.x4.shared.b16 {%0,%1,%2,%3}, [%4];"\
                 : "=r"(d0), "=r"(d1), "=r"(d2), "=r"(d3) : "r"(a))
#define LDSM2(d0, d1, a)                                                        \
    asm volatile("ldmatrix.sync.aligned.m8n8.x2.shared.b16 {%0,%1}, [%2];"      \
                 : "=r"(d0), "=r"(d1) : "r"(a))
#define CP16(dst, src)                                                          \
    asm volatile("cp.async.cg.shared.global [%0], [%1], 16;" :: "r"(dst), "l"(src))
#define CPCOMMIT() asm volatile("cp.async.commit_group;" ::: "memory")
#define CPWAIT()   asm volatile("cp.async.wait_group 0;" ::: "memory")

// -------- transpose x [B,I,T] -> xt [T,B,I] --------
__global__ void transpose_x(const float* __restrict__ x) {
    __shared__ float tile[32][33];
    int b = blockIdx.z, i0 = blockIdx.y * 32, t0 = blockIdx.x * 32;
    int tx = threadIdx.x, ty = threadIdx.y;
#pragma unroll
    for (int r = ty; r < 32; r += 8)
        tile[r][tx] = x[(size_t)b * Iz * Tz + (size_t)(i0 + r) * Tz + t0 + tx];
    __syncthreads();
#pragma unroll
    for (int r = ty; r < 32; r += 8)
        g_xt[(size_t)(t0 + r) * Bz * Iz + (size_t)b * Iz + i0 + tx] = tile[tx][r];
}

// ======== tf32 mma.sync GEMM: C[M,Gz] = A[M,K] @ W[Gz,K]^T + bi + bh ========
__global__ __launch_bounds__(256) void gemm_xg_mma(
    const float* __restrict__ A, const float* __restrict__ W,
    const float* __restrict__ bi, const float* __restrict__ bh,
    float* __restrict__ C, int K)
{
    __shared__ uint32_t As[128 * 36];
    __shared__ uint32_t Bs[128 * 36];

    int tid = threadIdx.x;
    int wid = tid >> 5, lane = tid & 31;
    int gid = lane >> 2, tig = lane & 3;
    int n0 = blockIdx.x * 128, m0 = blockIdx.y * 128;
    int mwarp = (wid >> 1) * 32;
    int nwarp = (wid & 1) * 64;

    float c[2][8][4];
#pragma unroll
    for (int mt = 0; mt < 2; mt++)
#pragma unroll
        for (int nt = 0; nt < 8; nt++)
#pragma unroll
            for (int q = 0; q < 4; q++) c[mt][nt][q] = 0.f;

    for (int k0 = 0; k0 < K; k0 += 32) {
#pragma unroll
        for (int j = 0; j < 4; j++) {
            int i = tid + j * 256;
            int row = i >> 3, q = i & 7;
            float4 v = *(const float4*)&A[(size_t)(m0 + row) * K + k0 + q * 4];
            uint4 t;
            t.x = f2tf32(v.x); t.y = f2tf32(v.y); t.z = f2tf32(v.z); t.w = f2tf32(v.w);
            *(uint4*)&As[row * 36 + q * 4] = t;
        }
#pragma unroll
        for (int j = 0; j < 4; j++) {
            int i = tid + j * 256;
            int row = i >> 3, q = i & 7;
            float4 v = *(const float4*)&W[(size_t)(n0 + row) * K + k0 + q * 4];
            uint4 t;
            t.x = f2tf32(v.x); t.y = f2tf32(v.y); t.z = f2tf32(v.z); t.w = f2tf32(v.w);
            *(uint4*)&Bs[row * 36 + q * 4] = t;
        }
        __syncthreads();

#pragma unroll
        for (int kk = 0; kk < 32; kk += 8) {
            uint32_t a[2][4];
#pragma unroll
            for (int mt = 0; mt < 2; mt++) {
                int mrow = mwarp + mt * 16;
                a[mt][0] = As[(mrow + gid)     * 36 + kk + tig];
                a[mt][1] = As[(mrow + gid + 8) * 36 + kk + tig];
                a[mt][2] = As[(mrow + gid)     * 36 + kk + tig + 4];
                a[mt][3] = As[(mrow + gid + 8) * 36 + kk + tig + 4];
            }
#pragma unroll
            for (int nt = 0; nt < 8; nt++) {
                uint32_t b0 = Bs[(nwarp + nt * 8 + gid) * 36 + kk + tig];
                uint32_t b1 = Bs[(nwarp + nt * 8 + gid) * 36 + kk + tig + 4];
                mma_tf32(c[0][nt], a[0], b0, b1);
                mma_tf32(c[1][nt], a[1], b0, b1);
            }
        }
        __syncthreads();
    }

#pragma unroll
    for (int mt = 0; mt < 2; mt++) {
        int m = m0 + mwarp + mt * 16 + gid;
#pragma unroll
        for (int nt = 0; nt < 8; nt++) {
            int n = n0 + nwarp + nt * 8 + 2 * tig;
            float bs0 = bi[n] + bh[n];
            float bs1 = bi[n + 1] + bh[n + 1];
            float2 o0 = {c[mt][nt][0] + bs0, c[mt][nt][1] + bs1};
            float2 o1 = {c[mt][nt][2] + bs0, c[mt][nt][3] + bs1};
            *(float2*)&C[(size_t)m * Gz + n] = o0;
            *(float2*)&C[(size_t)(m + 8) * Gz + n] = o1;
        }
    }
}

__global__ void reset_bar() {
    if (threadIdx.x < 2) g_barcnt[threadIdx.x] = 0;
}

// ======== persistent recurrence — K-split bf16 tensor path, 8 warps ========
// 128 CTAs (dir = bx&1, cb = bx>>1 owns units u0..u0+7 -> 32 gate-cols).
// Warp w owns k-range [w*64,(w+1)*64) for ALL 32 cols; stages its own A k-slice
// via cp.async (per-warp sync only); partials reduced across 8 warps in SMEM.
#define RST 1040                      // smem row stride bytes (520 bf16)
#define RSM_WHI 0                     // [32 c][520]
#define RSM_WLO 33280
#define RSM_AHI 66560                 // [32 b][520]
#define RSM_ALO 99840
#define RSM_PS  133120                // float[8][32][36]
#define REC_SMEM_BYTES (133120 + 8 * 32 * 36 * 4)

__global__ __launch_bounds__(256) void lstm_rec(
    const float* __restrict__ Wf, const float* __restrict__ Wb,
    float* __restrict__ outbuf, int st_t, int st_b)
{
    extern __shared__ char smr[];
    uint32_t sbase = smem_u32(smr);

    int dir = blockIdx.x & 1;
    int cb = blockIdx.x >> 1;
    int u0 = cb * 8;
    const float* W = dir ? Wb : Wf;
    const float* xg = dir ? g_xg1 : g_xg0;
    unsigned* cnt = &g_barcnt[dir];
    int tid = threadIdx.x;
    int wid = tid >> 5, l = tid & 31;
    int gid = l >> 2, tig = l & 3;

    // ---- split this CTA's 32 W_hh rows into bf16 hi/lo SMEM planes (once) ----
    {
        int c = tid >> 3, kq = tid & 7;
        const float* wrow = W + (size_t)((c >> 3) * Hz + u0 + (c & 7)) * Hz;
        unsigned short* whi = (unsigned short*)(smr + RSM_WHI);
        unsigned short* wlo = (unsigned short*)(smr + RSM_WLO);
#pragma unroll 4
        for (int p = 0; p < 16; p++) {
            int k = p * 32 + kq * 4;
            float4 v = *(const float4*)&wrow[k];
            float vv[4] = {v.x, v.y, v.z, v.w};
#pragma unroll
            for (int j = 0; j < 4; j++) {
                __nv_bfloat16 hb = __float2bfloat16(vv[j]);
                whi[c * 520 + k + j] = __bfloat16_as_ushort(hb);
                wlo[c * 520 + k + j] = __bfloat16_as_ushort(
                    __float2bfloat16(vv[j] - __bfloat162float(hb)));
            }
        }
    }

    // ---- zero h parity-0 planes (this CTA's 1/64 slice) ----
    g_hhi[dir][0][cb * 256 + tid] = 0;
    g_hlo[dir][0][cb * 256 + tid] = 0;
    float creg = 0.f;

    // init barrier
    __syncthreads();
    if (tid == 0) {
        __threadfence();
        asm volatile("red.global.gpu.add.u32 [%0], 1;" :: "l"(cnt) : "memory");
        unsigned v;
        do { asm volatile("ld.acquire.gpu.u32 %0, [%1];" : "=r"(v) : "l"(cnt) : "memory"); }
        while (v < 64u);
    }
    __syncthreads();

    // ldmatrix bases (warp k-offset = wid*64 k = wid*128 bytes)
    uint32_t abase = sbase + RSM_AHI + (uint32_t)(l & 15) * RST
                   + (uint32_t)((l >> 4) * 16) + (uint32_t)wid * 128;
    uint32_t bbase = sbase + RSM_WHI + (uint32_t)(l & 7) * RST
                   + (uint32_t)(((l >> 3) & 1) * 16) + (uint32_t)wid * 128;
    float* ps = (float*)(smr + RSM_PS);
    int bb = tid >> 3, uul = tid & 7;          // this thread's (batch, unit)

    // prefetch xg for step 0
    float xv[4];
    {
        int t0v = dir ? (Tz - 1) : 0;
        const float* xr = xg + (size_t)t0v * Bz * Gz + (size_t)bb * Gz + u0 + uul;
        xv[0] = xr[0 * Hz]; xv[1] = xr[1 * Hz]; xv[2] = xr[2 * Hz]; xv[3] = xr[3 * Hz];
    }

    for (int s = 0; s < Tz; s++) {
        int rb = s & 1;
        int wb = rb ^ 1;
        int t = dir ? (Tz - 1 - s) : s;

        // ---- per-warp staging: this warp's k-slice of h hi/lo (cp.async) ----
        {
            const char* hhi = (const char*)g_hhi[dir][rb];
            const char* hlo = (const char*)g_hlo[dir][rb];
            int co = wid * 128 + (l & 7) * 16;
#pragma unroll
            for (int j = 0; j < 8; j++) {
                int row = j * 4 + (l >> 3);
                CP16(sbase + RSM_AHI + row * RST + co, hhi + row * 1024 + co);
                CP16(sbase + RSM_ALO + row * RST + co, hlo + row * 1024 + co);
            }
            CPCOMMIT();
            CPWAIT();
            __syncwarp();
        }

        // ---- partial gates: 32b x 32cols over this warp's k64, 3-mma split ----
        float c[2][4][4];
#pragma unroll
        for (int mt = 0; mt < 2; mt++)
#pragma unroll
            for (int nt = 0; nt < 4; nt++)
#pragma unroll
                for (int q = 0; q < 4; q++) c[mt][nt][q] = 0.f;

#pragma unroll
        for (int ki = 0; ki < 4; ki++) {
            uint32_t ko = ki * 32;
            uint32_t ah[8], al[8];
            LDSM4(ah[0], ah[1], ah[2], ah[3], abase + ko);
            LDSM4(ah[4], ah[5], ah[6], ah[7], abase + 16 * RST + ko);
            LDSM4(al[0], al[1], al[2], al[3], abase + 33280 + ko);
            LDSM4(al[4], al[5], al[6], al[7], abase + 33280 + 16 * RST + ko);
#pragma unroll
            for (int nt = 0; nt < 4; nt++) {
                uint32_t bh0, bh1, bl0, bl1;
                LDSM2(bh0, bh1, bbase + nt * 8 * RST + ko);
                LDSM2(bl0, bl1, bbase + 33280 + nt * 8 * RST + ko);
                mma_bf16(c[0][nt], ah,     bh0, bh1);
                mma_bf16(c[1][nt], ah + 4, bh0, bh1);
                mma_bf16(c[0][nt], ah,     bl0, bl1);
                mma_bf16(c[1][nt], ah + 4, bl0, bl1);
                mma_bf16(c[0][nt], al,     bh0, bh1);
                mma_bf16(c[1][nt], al + 4, bh0, bh1);
            }
        }

        // ---- scatter partials to ps[wid][32][36] ----
        {
            float* pw = ps + wid * (32 * 36);
#pragma unroll
            for (int nt = 0; nt < 4; nt++) {
                int col = nt * 8 + 2 * tig;
                float2 v;
                v.x = c[0][nt][0]; v.y = c[0][nt][1];
                *(float2*)&pw[(gid)      * 36 + col] = v;
                v.x = c[0][nt][2]; v.y = c[0][nt][3];
                *(float2*)&pw[(gid + 8)  * 36 + col] = v;
                v.x = c[1][nt][0]; v.y = c[1][nt][1];
                *(float2*)&pw[(gid + 16) * 36 + col] = v;
                v.x = c[1][nt][2]; v.y = c[1][nt][3];
                *(float2*)&pw[(gid + 24) * 36 + col] = v;
            }
        }
        __syncthreads();

        // ---- reduce 8 partials + gates + state update (1 (b,u) per thread) ----
        float hn;
        {
            float gv4[4];
#pragma unroll
            for (int g = 0; g < 4; g++) {
                int base = bb * 36 + g * 8 + uul;
                float acc = xv[g];
#pragma unroll
                for (int w = 0; w < 8; w++) acc += ps[base + w * 1152];
                gv4[g] = acc;
            }
            float iv = sigf(gv4[0]), fv = sigf(gv4[1]);
            float gg = tanhf_(gv4[2]), ov = sigf(gv4[3]);
            float cn = fv * creg + iv * gg;
            hn = ov * tanhf_(cn);
            creg = cn;
            __nv_bfloat16 hb = __float2bfloat16(hn);
            g_hhi[dir][wb][bb * 512 + u0 + uul] = __bfloat16_as_ushort(hb);
            g_hlo[dir][wb][bb * 512 + u0 + uul] = __bfloat16_as_ushort(
                __float2bfloat16(hn - __bfloat162float(hb)));
        }

        // ---- arrive, then off-critical-path work, then wait ----
        __syncthreads();
        if (tid == 0) {
            __threadfence();
            asm volatile("red.global.gpu.add.u32 [%0], 1;" :: "l"(cnt) : "memory");
        }
        // outbuf store + next-step xg prefetch happen while the barrier fills
        outbuf[(size_t)t * st_t + (size_t)bb * st_b + dir * Hz + u0 + uul] = hn;
        if (s + 1 < Tz) {
            int tn = dir ? (Tz - 2 - s) : (s + 1);
            const float* xr = xg + (size_t)tn * Bz * Gz + (size_t)bb * Gz + u0 + uul;
            xv[0] = xr[0 * Hz]; xv[1] = xr[1 * Hz];
            xv[2] = xr[2 * Hz]; xv[3] = xr[3 * Hz];
        }
        if (tid == 0) {
            unsigned v, tgt = 64u * (unsigned)(s + 2);
            do { asm volatile("ld.acquire.gpu.u32 %0, [%1];" : "=r"(v) : "l"(cnt) : "memory"); }
            while (v < tgt);
        }
        __syncthreads();
    }

    g_cbuf[dir][bb * Hz + u0 + uul] = creg;
}

// -------- copy final h/c into h_n / c_n sections of d_out --------
__global__ void copy_state(float* __restrict__ dout, int layer) {
    int idx = blockIdx.x * 256 + threadIdx.x;   // 0..32767
    int d = idx >> 14;
    int r = idx & 16383;           // r = b*512 + u
    const size_t OUT = (size_t)Bz * Tz * 2 * Hz;
    float hv = __bfloat162float(__ushort_as_bfloat16(g_hhi[d][0][r]))
             + __bfloat162float(__ushort_as_bfloat16(g_hlo[d][0][r]));
    dout[OUT + (size_t)(2 * layer + d) * (Bz * Hz) + r] = hv;
    dout[OUT + 4 * (size_t)(Bz * Hz) + (size_t)(2 * layer + d) * (Bz * Hz) + r] = g_cbuf[d][r];
}

extern "C" void kernel_launch(void* const* d_in, const int* in_sizes, int n_in,
                              void* d_out, int out_size)
{
    const float* x        = (const float*)d_in[0];
    const float* w_ih_l0  = (const float*)d_in[1];
    const float* w_hh_l0  = (const float*)d_in[2];
    const float* b_ih_l0  = (const float*)d_in[3];
    const float* b_hh_l0  = (const float*)d_in[4];
    const float* w_ih_l0r = (const float*)d_in[5];
    const float* w_hh_l0r = (const float*)d_in[6];
    const float* b_ih_l0r = (const float*)d_in[7];
    const float* b_hh_l0r = (const float*)d_in[8];
    const float* w_ih_l1  = (const float*)d_in[9];
    const float* w_hh_l1  = (const float*)d_in[10];
    const float* b_ih_l1  = (const float*)d_in[11];
    const float* b_hh_l1  = (const float*)d_in[12];
    const float* w_ih_l1r = (const float*)d_in[13];
    const float* w_hh_l1r = (const float*)d_in[14];
    const float* b_ih_l1r = (const float*)d_in[15];
    const float* b_hh_l1r = (const float*)d_in[16];
    float* out = (float*)d_out;

    void* p;
    float *xt, *y0, *xg0, *xg1;
    cudaGetSymbolAddress(&p, g_xt);   xt  = (float*)p;
    cudaGetSymbolAddress(&p, g_y0);   y0  = (float*)p;
    cudaGetSymbolAddress(&p, g_xg0);  xg0 = (float*)p;
    cudaGetSymbolAddress(&p, g_xg1);  xg1 = (float*)p;

    cudaFuncSetAttribute(lstm_rec, cudaFuncAttributeMaxDynamicSharedMemorySize,
                         REC_SMEM_BYTES);

    // x [B,I,T] -> xt [T,B,I]
    transpose_x<<<dim3(Tz / 32, Iz / 32, Bz), dim3(32, 8)>>>(x);

    dim3 gg(Gz / 128, TB / 128);   // (16, 128)

    // ---- layer 0 ----
    gemm_xg_mma<<<gg, 256>>>(xt, w_ih_l0,  b_ih_l0,  b_hh_l0,  xg0, Iz);
    gemm_xg_mma<<<gg, 256>>>(xt, w_ih_l0r, b_ih_l0r, b_hh_l0r, xg1, Iz);
    reset_bar<<<1, 32>>>();
    lstm_rec<<<128, 256, REC_SMEM_BYTES>>>(w_hh_l0, w_hh_l0r, y0,
                                           Bz * 2 * Hz, 2 * Hz);
    copy_state<<<128, 256>>>(out, 0);

    // ---- layer 1 ----
    gemm_xg_mma<<<gg, 256>>>(y0, w_ih_l1,  b_ih_l1,  b_hh_l1,  xg0, 2 * Hz);
    gemm_xg_mma<<<gg, 256>>>(y0, w_ih_l1r, b_ih_l1r, b_hh_l1r, xg1, 2 * Hz);
    reset_bar<<<1, 32>>>();
    lstm_rec<<<128, 256, REC_SMEM_BYTES>>>(w_hh_l1, w_hh_l1r, out,
                                           2 * Hz, Tz * 2 * Hz);
    copy_state<<<128, 256>>>(out, 1);
}

// round 9
// speedup vs baseline: 3.3155x; 1.0003x over previous
#include <cuda_runtime.h>
#include <cuda_bf16.h>
#include <cstdint>

#define Tz 512
#define Bz 32
#define Iz 256
#define Hz 512
#define Gz 2048          // 4*H
#define TB (Tz*Bz)       // 16384

// -------- scratch (device globals; no runtime allocation) --------
__device__ float g_xt[(size_t)TB * Iz];        // x transposed to [T,B,I]
__device__ float g_xg0[(size_t)TB * Gz];       // fwd-dir input-gate projections
__device__ float g_xg1[(size_t)TB * Gz];       // bwd-dir input-gate projections
__device__ float g_y0[(size_t)TB * 2 * Hz];    // layer-0 output [T,B,2H]
__device__ unsigned short g_hhi[2][2][Bz * Hz]; // [dir][parity][b*512+u] bf16 hi
__device__ unsigned short g_hlo[2][2][Bz * Hz]; // [dir][parity][b*512+u] bf16 lo
__device__ float g_cbuf[2][Bz * Hz];           // [dir][b*H+u]
__device__ unsigned g_barcnt[2];               // per-direction arrival counters

__device__ __forceinline__ float sigf(float x) { return 1.f / (1.f + __expf(-x)); }
__device__ __forceinline__ float tanhf_(float x) { return 2.f / (1.f + __expf(-2.f * x)) - 1.f; }

__device__ __forceinline__ uint32_t f2tf32(float f) {
    uint32_t r;
    asm("cvt.rna.tf32.f32 %0, %1;" : "=r"(r) : "f"(f));
    return r;
}

__device__ __forceinline__ uint32_t smem_u32(const void* p) {
    uint32_t a;
    asm("{ .reg .u64 t; cvta.to.shared.u64 t, %1; cvt.u32.u64 %0, t; }" : "=r"(a) : "l"(p));
    return a;
}

// mma.sync tf32 m16n8k8 (input GEMMs)
__device__ __forceinline__ void mma_tf32(float* c, const uint32_t* a,
                                         uint32_t b0, uint32_t b1) {
    asm volatile(
        "mma.sync.aligned.m16n8k8.row.col.f32.tf32.tf32.f32 "
        "{%0,%1,%2,%3}, {%4,%5,%6,%7}, {%8,%9}, {%0,%1,%2,%3};"
        : "+f"(c[0]), "+f"(c[1]), "+f"(c[2]), "+f"(c[3])
        : "r"(a[0]), "r"(a[1]), "r"(a[2]), "r"(a[3]), "r"(b0), "r"(b1));
}

// mma.sync bf16 m16n8k16 (recurrence)
__device__ __forceinline__ void mma_bf16(float* c, const uint32_t* a,
                                         uint32_t b0, uint32_t b1) {
    asm volatile(
        "mma.sync.aligned.m16n8k16.row.col.f32.bf16.bf16.f32 "
        "{%0,%1,%2,%3}, {%4,%5,%6,%7}, {%8,%9}, {%0,%1,%2,%3};"
        : "+f"(c[0]), "+f"(c[1]), "+f"(c[2]), "+f"(c[3])
        : "r"(a[0]), "r"(a[1]), "r"(a[2]), "r"(a[3]), "r"(b0), "r"(b1));
}

#define LDSM4(d0, d1, d2, d3, a)                                                \
    asm volatile("ldmatrix.sync.aligned.m8n8.x4.shared.b16 {%0,%1,%2,%3}, [%4];"\
                 : "=r"(d0), "=r"(d1), "=r"(d2), "=r"(d3) : "r"(a))
#define LDSM2(d0, d1, a)                                                        \
    asm volatile("ldmatrix.sync.aligned.m8n8.x2.shared.b16 {%0,%1}, [%2];"      \
                 : "=r"(d0), "=r"(d1) : "r"(a))
#define CP16(dst, src)                                                          \
    asm volatile("cp.async.cg.shared.global [%0], [%1], 16;" :: "r"(dst), "l"(src))
#define CPCOMMIT() asm volatile("cp.async.commit_group;" ::: "memory")

template <int N>
__device__ __forceinline__ void cpwaitg() {
    asm volatile("cp.async.wait_group %0;" :: "n"(N) : "memory");
}

// -------- transpose x [B,I,T] -> xt [T,B,I] --------
__global__ void transpose_x(const float* __restrict__ x) {
    __shared__ float tile[32][33];
    int b = blockIdx.z, i0 = blockIdx.y * 32, t0 = blockIdx.x * 32;
    int tx = threadIdx.x, ty = threadIdx.y;
#pragma unroll
    for (int r = ty; r < 32; r += 8)
        tile[r][tx] = x[(size_t)b * Iz * Tz + (size_t)(i0 + r) * Tz + t0 + tx];
    __syncthreads();
#pragma unroll
    for (int r = ty; r < 32; r += 8)
        g_xt[(size_t)(t0 + r) * Bz * Iz + (size_t)b * Iz + i0 + tx] = tile[tx][r];
}

// ======== tf32 mma.sync GEMM: C[M,Gz] = A[M,K] @ W[Gz,K]^T + bi + bh ========
// register-prefetch pipeline: next chunk's global loads issued under current mma
__global__ __launch_bounds__(256) void gemm_xg_mma(
    const float* __restrict__ A, const float* __restrict__ W,
    const float* __restrict__ bi, const float* __restrict__ bh,
    float* __restrict__ C, int K)
{
    __shared__ uint32_t As[128 * 36];
    __shared__ uint32_t Bs[128 * 36];

    int tid = threadIdx.x;
    int wid = tid >> 5, lane = tid & 31;
    int gid = lane >> 2, tig = lane & 3;
    int n0 = blockIdx.x * 128, m0 = blockIdx.y * 128;
    int mwarp = (wid >> 1) * 32;
    int nwarp = (wid & 1) * 64;
    int lrow = tid >> 3, lq = tid & 7;

    float c[2][8][4];
#pragma unroll
    for (int mt = 0; mt < 2; mt++)
#pragma unroll
        for (int nt = 0; nt < 8; nt++)
#pragma unroll
            for (int q = 0; q < 4; q++) c[mt][nt][q] = 0.f;

    float4 pa[4], pb[4];
#pragma unroll
    for (int j = 0; j < 4; j++) {
        pa[j] = *(const float4*)&A[(size_t)(m0 + lrow + j * 32) * K + lq * 4];
        pb[j] = *(const float4*)&W[(size_t)(n0 + lrow + j * 32) * K + lq * 4];
    }

    for (int k0 = 0; k0 < K; k0 += 32) {
#pragma unroll
        for (int j = 0; j < 4; j++) {
            uint4 ta, tb;
            ta.x = f2tf32(pa[j].x); ta.y = f2tf32(pa[j].y);
            ta.z = f2tf32(pa[j].z); ta.w = f2tf32(pa[j].w);
            tb.x = f2tf32(pb[j].x); tb.y = f2tf32(pb[j].y);
            tb.z = f2tf32(pb[j].z); tb.w = f2tf32(pb[j].w);
            *(uint4*)&As[(lrow + j * 32) * 36 + lq * 4] = ta;
            *(uint4*)&Bs[(lrow + j * 32) * 36 + lq * 4] = tb;
        }
        __syncthreads();

        if (k0 + 32 < K) {
#pragma unroll
            for (int j = 0; j < 4; j++) {
                pa[j] = *(const float4*)&A[(size_t)(m0 + lrow + j * 32) * K + k0 + 32 + lq * 4];
                pb[j] = *(const float4*)&W[(size_t)(n0 + lrow + j * 32) * K + k0 + 32 + lq * 4];
            }
        }

#pragma unroll
        for (int kk = 0; kk < 32; kk += 8) {
            uint32_t a[2][4];
#pragma unroll
            for (int mt = 0; mt < 2; mt++) {
                int mrow = mwarp + mt * 16;
                a[mt][0] = As[(mrow + gid)     * 36 + kk + tig];
                a[mt][1] = As[(mrow + gid + 8) * 36 + kk + tig];
                a[mt][2] = As[(mrow + gid)     * 36 + kk + tig + 4];
                a[mt][3] = As[(mrow + gid + 8) * 36 + kk + tig + 4];
            }
#pragma unroll
            for (int nt = 0; nt < 8; nt++) {
                uint32_t b0 = Bs[(nwarp + nt * 8 + gid) * 36 + kk + tig];
                uint32_t b1 = Bs[(nwarp + nt * 8 + gid) * 36 + kk + tig + 4];
                mma_tf32(c[0][nt], a[0], b0, b1);
                mma_tf32(c[1][nt], a[1], b0, b1);
            }
        }
        __syncthreads();
    }

#pragma unroll
    for (int mt = 0; mt < 2; mt++) {
        int m = m0 + mwarp + mt * 16 + gid;
#pragma unroll
        for (int nt = 0; nt < 8; nt++) {
            int n = n0 + nwarp + nt * 8 + 2 * tig;
            float bs0 = bi[n] + bh[n];
            float bs1 = bi[n + 1] + bh[n + 1];
            float2 o0 = {c[mt][nt][0] + bs0, c[mt][nt][1] + bs1};
            float2 o1 = {c[mt][nt][2] + bs0, c[mt][nt][3] + bs1};
            *(float2*)&C[(size_t)m * Gz + n] = o0;
            *(float2*)&C[(size_t)(m + 8) * Gz + n] = o1;
        }
    }
}

__global__ void reset_bar() {
    if (threadIdx.x < 2) g_barcnt[threadIdx.x] = 0;
}

// ======== persistent recurrence — K-split bf16 tensor path, 8 warps ========
// W fragments hoisted to registers (step-invariant); staging pipelined in 4
// cp.async commit groups overlapping ldmatrix/mma; ps stride 40 (conflict-free).
#define RST 1040                      // smem row stride bytes (520 bf16)
#define RSM_WHI 0                     // [32 c][520]
#define RSM_WLO 33280
#define RSM_AHI 66560                 // [32 b][520]
#define RSM_ALO 99840
#define RSM_PS  133120                // float[8][32][40]
#define REC_SMEM_BYTES (133120 + 8 * 32 * 40 * 4)

#define REC_KI(ki, wg) {                                                        \
    cpwaitg<wg>();                                                              \
    __syncwarp();                                                               \
    uint32_t ah[8], al[8];                                                      \
    LDSM4(ah[0], ah[1], ah[2], ah[3], abase + (ki) * 32);                       \
    LDSM4(ah[4], ah[5], ah[6], ah[7], abase + 16 * RST + (ki) * 32);            \
    LDSM4(al[0], al[1], al[2], al[3], abase + 33280 + (ki) * 32);               \
    LDSM4(al[4], al[5], al[6], al[7], abase + 33280 + 16 * RST + (ki) * 32);    \
    _Pragma("unroll")                                                           \
    for (int nt = 0; nt < 4; nt++) {                                            \
        uint32_t bh0 = wf[(ki) * 16 + nt * 4 + 0];                              \
        uint32_t bh1 = wf[(ki) * 16 + nt * 4 + 1];                              \
        uint32_t bl0 = wf[(ki) * 16 + nt * 4 + 2];                              \
        uint32_t bl1 = wf[(ki) * 16 + nt * 4 + 3];                              \
        mma_bf16(c[0][nt], ah,     bh0, bh1);                                   \
        mma_bf16(c[1][nt], ah + 4, bh0, bh1);                                   \
        mma_bf16(c[0][nt], ah,     bl0, bl1);                                   \
        mma_bf16(c[1][nt], ah + 4, bl0, bl1);                                   \
        mma_bf16(c[0][nt], al,     bh0, bh1);                                   \
        mma_bf16(c[1][nt], al + 4, bh0, bh1);                                   \
    }                                                                           \
}

__global__ __launch_bounds__(256, 1) void lstm_rec(
    const float* __restrict__ Wf, const float* __restrict__ Wb,
    float* __restrict__ outbuf, int st_t, int st_b)
{
    extern __shared__ char smr[];
    uint32_t sbase = smem_u32(smr);

    int dir = blockIdx.x & 1;
    int cb = blockIdx.x >> 1;
    int u0 = cb * 8;
    const float* W = dir ? Wb : Wf;
    const float* xg = dir ? g_xg1 : g_xg0;
    unsigned* cnt = &g_barcnt[dir];
    int tid = threadIdx.x;
    int wid = tid >> 5, l = tid & 31;
    int gid = l >> 2, tig = l & 3;

    // ---- split this CTA's 32 W_hh rows into bf16 hi/lo SMEM planes (once) ----
    {
        int c = tid >> 3, kq = tid & 7;
        const float* wrow = W + (size_t)((c >> 3) * Hz + u0 + (c & 7)) * Hz;
        unsigned short* whi = (unsigned short*)(smr + RSM_WHI);
        unsigned short* wlo = (unsigned short*)(smr + RSM_WLO);
#pragma unroll 4
        for (int p = 0; p < 16; p++) {
            int k = p * 32 + kq * 4;
            float4 v = *(const float4*)&wrow[k];
            float vv[4] = {v.x, v.y, v.z, v.w};
#pragma unroll
            for (int j = 0; j < 4; j++) {
                __nv_bfloat16 hb = __float2bfloat16(vv[j]);
                whi[c * 520 + k + j] = __bfloat16_as_ushort(hb);
                wlo[c * 520 + k + j] = __bfloat16_as_ushort(
                    __float2bfloat16(vv[j] - __bfloat162float(hb)));
            }
        }
    }

    // ---- zero h parity-0 planes (this CTA's 1/64 slice) ----
    g_hhi[dir][0][cb * 256 + tid] = 0;
    g_hlo[dir][0][cb * 256 + tid] = 0;
    float creg = 0.f;

    // init barrier
    __syncthreads();
    if (tid == 0) {
        asm volatile("red.release.gpu.global.add.u32 [%0], 1;" :: "l"(cnt) : "memory");
        unsigned v;
        do { asm volatile("ld.acquire.gpu.u32 %0, [%1];" : "=r"(v) : "l"(cnt) : "memory"); }
        while (v < 64u);
    }
    __syncthreads();

    // ldmatrix bases (warp k-offset = wid*64 k = wid*128 bytes)
    uint32_t abase = sbase + RSM_AHI + (uint32_t)(l & 15) * RST
                   + (uint32_t)((l >> 4) * 16) + (uint32_t)wid * 128;
    uint32_t bbase = sbase + RSM_WHI + (uint32_t)(l & 7) * RST
                   + (uint32_t)(((l >> 3) & 1) * 16) + (uint32_t)wid * 128;
    float* ps = (float*)(smr + RSM_PS);
    int bb = tid >> 3, uul = tid & 7;          // this thread's (batch, unit)

    // ---- hoist W fragments into registers (step-invariant) ----
    uint32_t wf[64];
#pragma unroll
    for (int ki = 0; ki < 4; ki++)
#pragma unroll
        for (int nt = 0; nt < 4; nt++) {
            LDSM2(wf[ki * 16 + nt * 4 + 0], wf[ki * 16 + nt * 4 + 1],
                  bbase + nt * 8 * RST + ki * 32);
            LDSM2(wf[ki * 16 + nt * 4 + 2], wf[ki * 16 + nt * 4 + 3],
                  bbase + 33280 + nt * 8 * RST + ki * 32);
        }

    // prefetch xg for step 0
    float xv[4];
    {
        int t0v = dir ? (Tz - 1) : 0;
        const float* xr = xg + (size_t)t0v * Bz * Gz + (size_t)bb * Gz + u0 + uul;
        xv[0] = xr[0 * Hz]; xv[1] = xr[1 * Hz]; xv[2] = xr[2 * Hz]; xv[3] = xr[3 * Hz];
    }

    for (int s = 0; s < Tz; s++) {
        int rb = s & 1;
        int wb = rb ^ 1;
        int t = dir ? (Tz - 1 - s) : s;

        // ---- per-warp pipelined staging: 4 commit groups (one per ki) ----
        {
            const char* hhi = (const char*)g_hhi[dir][rb];
            const char* hlo = (const char*)g_hlo[dir][rb];
            int r0 = l >> 1;
#pragma unroll
            for (int g = 0; g < 4; g++) {
                int co = wid * 128 + g * 32 + (l & 1) * 16;
                CP16(sbase + RSM_AHI + r0 * RST + co,        hhi + r0 * 1024 + co);
                CP16(sbase + RSM_AHI + (r0 + 16) * RST + co, hhi + (r0 + 16) * 1024 + co);
                CP16(sbase + RSM_ALO + r0 * RST + co,        hlo + r0 * 1024 + co);
                CP16(sbase + RSM_ALO + (r0 + 16) * RST + co, hlo + (r0 + 16) * 1024 + co);
                CPCOMMIT();
            }
        }

        // ---- partial gates: 32b x 32cols over this warp's k64, 3-mma split ----
        float c[2][4][4];
#pragma unroll
        for (int mt = 0; mt < 2; mt++)
#pragma unroll
            for (int nt = 0; nt < 4; nt++)
#pragma unroll
                for (int q = 0; q < 4; q++) c[mt][nt][q] = 0.f;

        REC_KI(0, 3)
        REC_KI(1, 2)
        REC_KI(2, 1)
        REC_KI(3, 0)

        // ---- scatter partials to ps[wid][32][40] ----
        {
            float* pw = ps + wid * (32 * 40);
#pragma unroll
            for (int nt = 0; nt < 4; nt++) {
                int col = nt * 8 + 2 * tig;
                float2 v;
                v.x = c[0][nt][0]; v.y = c[0][nt][1];
                *(float2*)&pw[(gid)      * 40 + col] = v;
                v.x = c[0][nt][2]; v.y = c[0][nt][3];
                *(float2*)&pw[(gid + 8)  * 40 + col] = v;
                v.x = c[1][nt][0]; v.y = c[1][nt][1];
                *(float2*)&pw[(gid + 16) * 40 + col] = v;
                v.x = c[1][nt][2]; v.y = c[1][nt][3];
                *(float2*)&pw[(gid + 24) * 40 + col] = v;
            }
        }
        __syncthreads();

        // ---- reduce 8 partials + gates + state update (1 (b,u) per thread) ----
        float hn;
        {
            float gv4[4];
#pragma unroll
            for (int g = 0; g < 4; g++) {
                int base = bb * 40 + g * 8 + uul;
                float acc = xv[g];
#pragma unroll
                for (int w = 0; w < 8; w++) acc += ps[base + w * 1280];
                gv4[g] = acc;
            }
            float iv = sigf(gv4[0]), fv = sigf(gv4[1]);
            float gg = tanhf_(gv4[2]), ov = sigf(gv4[3]);
            float cn = fv * creg + iv * gg;
            hn = ov * tanhf_(cn);
            creg = cn;
            __nv_bfloat16 hb = __float2bfloat16(hn);
            g_hhi[dir][wb][bb * 512 + u0 + uul] = __bfloat16_as_ushort(hb);
            g_hlo[dir][wb][bb * 512 + u0 + uul] = __bfloat16_as_ushort(
                __float2bfloat16(hn - __bfloat162float(hb)));
        }

        // ---- arrive (release), then off-critical-path work, then wait ----
        __syncthreads();
        if (tid == 0) {
            asm volatile("red.release.gpu.global.add.u32 [%0], 1;" :: "l"(cnt) : "memory");
        }
        outbuf[(size_t)t * st_t + (size_t)bb * st_b + dir * Hz + u0 + uul] = hn;
        if (s + 1 < Tz) {
            int tn = dir ? (Tz - 2 - s) : (s + 1);
            const float* xr = xg + (size_t)tn * Bz * Gz + (size_t)bb * Gz + u0 + uul;
            xv[0] = xr[0 * Hz]; xv[1] = xr[1 * Hz];
            xv[2] = xr[2 * Hz]; xv[3] = xr[3 * Hz];
        }
        if (tid == 0) {
            unsigned v, tgt = 64u * (unsigned)(s + 2);
            do { asm volatile("ld.acquire.gpu.u32 %0, [%1];" : "=r"(v) : "l"(cnt) : "memory"); }
            while (v < tgt);
        }
        __syncthreads();
    }

    g_cbuf[dir][bb * Hz + u0 + uul] = creg;
}

// -------- copy final h/c into h_n / c_n sections of d_out --------
__global__ void copy_state(float* __restrict__ dout, int layer) {
    int idx = blockIdx.x * 256 + threadIdx.x;   // 0..32767
    int d = idx >> 14;
    int r = idx & 16383;           // r = b*512 + u
    const size_t OUT = (size_t)Bz * Tz * 2 * Hz;
    float hv = __bfloat162float(__ushort_as_bfloat16(g_hhi[d][0][r]))
             + __bfloat162float(__ushort_as_bfloat16(g_hlo[d][0][r]));
    dout[OUT + (size_t)(2 * layer + d) * (Bz * Hz) + r] = hv;
    dout[OUT + 4 * (size_t)(Bz * Hz) + (size_t)(2 * layer + d) * (Bz * Hz) + r] = g_cbuf[d][r];
}

extern "C" void kernel_launch(void* const* d_in, const int* in_sizes, int n_in,
                              void* d_out, int out_size)
{
    const float* x        = (const float*)d_in[0];
    const float* w_ih_l0  = (const float*)d_in[1];
    const float* w_hh_l0  = (const float*)d_in[2];
    const float* b_ih_l0  = (const float*)d_in[3];
    const float* b_hh_l0  = (const float*)d_in[4];
    const float* w_ih_l0r = (const float*)d_in[5];
    const float* w_hh_l0r = (const float*)d_in[6];
    const float* b_ih_l0r = (const float*)d_in[7];
    const float* b_hh_l0r = (const float*)d_in[8];
    const float* w_ih_l1  = (const float*)d_in[9];
    const float* w_hh_l1  = (const float*)d_in[10];
    const float* b_ih_l1  = (const float*)d_in[11];
    const float* b_hh_l1  = (const float*)d_in[12];
    const float* w_ih_l1r = (const float*)d_in[13];
    const float* w_hh_l1r = (const float*)d_in[14];
    const float* b_ih_l1r = (const float*)d_in[15];
    const float* b_hh_l1r = (const float*)d_in[16];
    float* out = (float*)d_out;

    void* p;
    float *xt, *y0, *xg0, *xg1;
    cudaGetSymbolAddress(&p, g_xt);   xt  = (float*)p;
    cudaGetSymbolAddress(&p, g_y0);   y0  = (float*)p;
    cudaGetSymbolAddress(&p, g_xg0);  xg0 = (float*)p;
    cudaGetSymbolAddress(&p, g_xg1);  xg1 = (float*)p;

    cudaFuncSetAttribute(lstm_rec, cudaFuncAttributeMaxDynamicSharedMemorySize,
                         REC_SMEM_BYTES);

    // x [B,I,T] -> xt [T,B,I]
    transpose_x<<<dim3(Tz / 32, Iz / 32, Bz), dim3(32, 8)>>>(x);

    dim3 gg(Gz / 128, TB / 128);   // (16, 128)

    // ---- layer 0 ----
    gemm_xg_mma<<<gg, 256>>>(xt, w_ih_l0,  b_ih_l0,  b_hh_l0,  xg0, Iz);
    gemm_xg_mma<<<gg, 256>>>(xt, w_ih_l0r, b_ih_l0r, b_hh_l0r, xg1, Iz);
    reset_bar<<<1, 32>>>();
    lstm_rec<<<128, 256, REC_SMEM_BYTES>>>(w_hh_l0, w_hh_l0r, y0,
                                           Bz * 2 * Hz, 2 * Hz);
    copy_state<<<128, 256>>>(out, 0);

    // ---- layer 1 ----
    gemm_xg_mma<<<gg, 256>>>(y0, w_ih_l1,  b_ih_l1,  b_hh_l1,  xg0, 2 * Hz);
    gemm_xg_mma<<<gg, 256>>>(y0, w_ih_l1r, b_ih_l1r, b_hh_l1r, xg1, 2 * Hz);
    reset_bar<<<1, 32>>>();
    lstm_rec<<<128, 256, REC_SMEM_BYTES>>>(w_hh_l1, w_hh_l1r, out,
                                           2 * Hz, Tz * 2 * Hz);
    copy_state<<<128, 256>>>(out, 1);
}

// round 10
// speedup vs baseline: 3.3509x; 1.0107x over previous
#include <cuda_runtime.h>
#include <cuda_bf16.h>
#include <cstdint>

#define Tz 512
#define Bz 32
#define Iz 256
#define Hz 512
#define Gz 2048          // 4*H
#define TB (Tz*Bz)       // 16384

// -------- scratch (device globals; no runtime allocation) --------
__device__ float g_xt[(size_t)TB * Iz];        // x transposed to [T,B,I]
__device__ float g_xg0[(size_t)TB * Gz];       // fwd-dir input-gate projections
__device__ float g_xg1[(size_t)TB * Gz];       // bwd-dir input-gate projections
__device__ float g_y0[(size_t)TB * 2 * Hz];    // layer-0 output [T,B,2H]
__device__ unsigned short g_hhi[2][2][Bz * Hz]; // [dir][parity][b*512+u] bf16 hi
__device__ unsigned short g_hlo[2][2][Bz * Hz]; // [dir][parity][b*512+u] bf16 lo
__device__ float g_cbuf[2][Bz * Hz];           // [dir][b*H+u]
__device__ unsigned g_flag[2][64];             // per-CTA publish counters

__device__ __forceinline__ float sigf(float x) { return 1.f / (1.f + __expf(-x)); }
__device__ __forceinline__ float tanhf_(float x) { return 2.f / (1.f + __expf(-2.f * x)) - 1.f; }

__device__ __forceinline__ uint32_t f2tf32(float f) {
    uint32_t r;
    asm("cvt.rna.tf32.f32 %0, %1;" : "=r"(r) : "f"(f));
    return r;
}

__device__ __forceinline__ uint32_t smem_u32(const void* p) {
    uint32_t a;
    asm("{ .reg .u64 t; cvta.to.shared.u64 t, %1; cvt.u32.u64 %0, t; }" : "=r"(a) : "l"(p));
    return a;
}

// mma.sync tf32 m16n8k8 (input GEMMs)
__device__ __forceinline__ void mma_tf32(float* c, const uint32_t* a,
                                         uint32_t b0, uint32_t b1) {
    asm volatile(
        "mma.sync.aligned.m16n8k8.row.col.f32.tf32.tf32.f32 "
        "{%0,%1,%2,%3}, {%4,%5,%6,%7}, {%8,%9}, {%0,%1,%2,%3};"
        : "+f"(c[0]), "+f"(c[1]), "+f"(c[2]), "+f"(c[3])
        : "r"(a[0]), "r"(a[1]), "r"(a[2]), "r"(a[3]), "r"(b0), "r"(b1));
}

// mma.sync bf16 m16n8k16 (recurrence)
__device__ __forceinline__ void mma_bf16(float* c, const uint32_t* a,
                                         uint32_t b0, uint32_t b1) {
    asm volatile(
        "mma.sync.aligned.m16n8k16.row.col.f32.bf16.bf16.f32 "
        "{%0,%1,%2,%3}, {%4,%5,%6,%7}, {%8,%9}, {%0,%1,%2,%3};"
        : "+f"(c[0]), "+f"(c[1]), "+f"(c[2]), "+f"(c[3])
        : "r"(a[0]), "r"(a[1]), "r"(a[2]), "r"(a[3]), "r"(b0), "r"(b1));
}

#define LDSM4(d0, d1, d2, d3, a)                                                \
    asm volatile("ldmatrix.sync.aligned.m8n8.x4.shared.b16 {%0,%1,%2,%3}, [%4];"\
                 : "=r"(d0), "=r"(d1), "=r"(d2), "=r"(d3) : "r"(a))
#define LDSM2(d0, d1, a)                                                        \
    asm volatile("ldmatrix.sync.aligned.m8n8.x2.shared.b16 {%0,%1}, [%2];"      \
                 : "=r"(d0), "=r"(d1) : "r"(a))
#define CP16(dst, src)                                                          \
    asm volatile("cp.async.cg.shared.global [%0], [%1], 16;" :: "r"(dst), "l"(src))
#define CPCOMMIT() asm volatile("cp.async.commit_group;" ::: "memory")

template <int N>
__device__ __forceinline__ void cpwaitg() {
    asm volatile("cp.async.wait_group %0;" :: "n"(N) : "memory");
}

// -------- transpose x [B,I,T] -> xt [T,B,I] --------
__global__ void transpose_x(const float* __restrict__ x) {
    __shared__ float tile[32][33];
    int b = blockIdx.z, i0 = blockIdx.y * 32, t0 = blockIdx.x * 32;
    int tx = threadIdx.x, ty = threadIdx.y;
#pragma unroll
    for (int r = ty; r < 32; r += 8)
        tile[r][tx] = x[(size_t)b * Iz * Tz + (size_t)(i0 + r) * Tz + t0 + tx];
    __syncthreads();
#pragma unroll
    for (int r = ty; r < 32; r += 8)
        g_xt[(size_t)(t0 + r) * Bz * Iz + (size_t)b * Iz + i0 + tx] = tile[tx][r];
}

// ======== tf32 mma.sync GEMM: C[M,Gz] = A[M,K] @ W[Gz,K]^T + bi + bh ========
__global__ __launch_bounds__(256) void gemm_xg_mma(
    const float* __restrict__ A, const float* __restrict__ W,
    const float* __restrict__ bi, const float* __restrict__ bh,
    float* __restrict__ C, int K)
{
    __shared__ uint32_t As[128 * 36];
    __shared__ uint32_t Bs[128 * 36];

    int tid = threadIdx.x;
    int wid = tid >> 5, lane = tid & 31;
    int gid = lane >> 2, tig = lane & 3;
    int n0 = blockIdx.x * 128, m0 = blockIdx.y * 128;
    int mwarp = (wid >> 1) * 32;
    int nwarp = (wid & 1) * 64;
    int lrow = tid >> 3, lq = tid & 7;

    float c[2][8][4];
#pragma unroll
    for (int mt = 0; mt < 2; mt++)
#pragma unroll
        for (int nt = 0; nt < 8; nt++)
#pragma unroll
            for (int q = 0; q < 4; q++) c[mt][nt][q] = 0.f;

    float4 pa[4], pb[4];
#pragma unroll
    for (int j = 0; j < 4; j++) {
        pa[j] = *(const float4*)&A[(size_t)(m0 + lrow + j * 32) * K + lq * 4];
        pb[j] = *(const float4*)&W[(size_t)(n0 + lrow + j * 32) * K + lq * 4];
    }

    for (int k0 = 0; k0 < K; k0 += 32) {
#pragma unroll
        for (int j = 0; j < 4; j++) {
            uint4 ta, tb;
            ta.x = f2tf32(pa[j].x); ta.y = f2tf32(pa[j].y);
            ta.z = f2tf32(pa[j].z); ta.w = f2tf32(pa[j].w);
            tb.x = f2tf32(pb[j].x); tb.y = f2tf32(pb[j].y);
            tb.z = f2tf32(pb[j].z); tb.w = f2tf32(pb[j].w);
            *(uint4*)&As[(lrow + j * 32) * 36 + lq * 4] = ta;
            *(uint4*)&Bs[(lrow + j * 32) * 36 + lq * 4] = tb;
        }
        __syncthreads();

        if (k0 + 32 < K) {
#pragma unroll
            for (int j = 0; j < 4; j++) {
                pa[j] = *(const float4*)&A[(size_t)(m0 + lrow + j * 32) * K + k0 + 32 + lq * 4];
                pb[j] = *(const float4*)&W[(size_t)(n0 + lrow + j * 32) * K + k0 + 32 + lq * 4];
            }
        }

#pragma unroll
        for (int kk = 0; kk < 32; kk += 8) {
            uint32_t a[2][4];
#pragma unroll
            for (int mt = 0; mt < 2; mt++) {
                int mrow = mwarp + mt * 16;
                a[mt][0] = As[(mrow + gid)     * 36 + kk + tig];
                a[mt][1] = As[(mrow + gid + 8) * 36 + kk + tig];
                a[mt][2] = As[(mrow + gid)     * 36 + kk + tig + 4];
                a[mt][3] = As[(mrow + gid + 8) * 36 + kk + tig + 4];
            }
#pragma unroll
            for (int nt = 0; nt < 8; nt++) {
                uint32_t b0 = Bs[(nwarp + nt * 8 + gid) * 36 + kk + tig];
                uint32_t b1 = Bs[(nwarp + nt * 8 + gid) * 36 + kk + tig + 4];
                mma_tf32(c[0][nt], a[0], b0, b1);
                mma_tf32(c[1][nt], a[1], b0, b1);
            }
        }
        __syncthreads();
    }

#pragma unroll
    for (int mt = 0; mt < 2; mt++) {
        int m = m0 + mwarp + mt * 16 + gid;
#pragma unroll
        for (int nt = 0; nt < 8; nt++) {
            int n = n0 + nwarp + nt * 8 + 2 * tig;
            float bs0 = bi[n] + bh[n];
            float bs1 = bi[n + 1] + bh[n + 1];
            float2 o0 = {c[mt][nt][0] + bs0, c[mt][nt][1] + bs1};
            float2 o1 = {c[mt][nt][2] + bs0, c[mt][nt][3] + bs1};
            *(float2*)&C[(size_t)m * Gz + n] = o0;
            *(float2*)&C[(size_t)(m + 8) * Gz + n] = o1;
        }
    }
}

__global__ void reset_flags() {
    if (threadIdx.x < 128) ((unsigned*)g_flag)[threadIdx.x] = 0;
}

// ======== persistent recurrence — K-split bf16, per-CTA dataflow flags ========
// Warp w consumes units 64w..64w+63 = outputs of producer CTAs 8w..8w+7 only;
// it spin-waits on exactly those 8 flags (distinct addresses, no serialization).
#define RST 1040                      // smem row stride bytes (520 bf16)
#define RSM_WHI 0                     // [32 c][520]
#define RSM_WLO 33280
#define RSM_AHI 66560                 // [32 b][520]
#define RSM_ALO 99840
#define RSM_PS  133120                // float[8][32][40]
#define REC_SMEM_BYTES (133120 + 8 * 32 * 40 * 4)

#define REC_KI(ki, wg) {                                                        \
    cpwaitg<wg>();                                                              \
    __syncwarp();                                                               \
    uint32_t ah[8], al[8];                                                      \
    LDSM4(ah[0], ah[1], ah[2], ah[3], abase + (ki) * 32);                       \
    LDSM4(ah[4], ah[5], ah[6], ah[7], abase + 16 * RST + (ki) * 32);            \
    LDSM4(al[0], al[1], al[2], al[3], abase + 33280 + (ki) * 32);               \
    LDSM4(al[4], al[5], al[6], al[7], abase + 33280 + 16 * RST + (ki) * 32);    \
    _Pragma("unroll")                                                           \
    for (int nt = 0; nt < 4; nt++) {                                            \
        uint32_t bh0 = wf[(ki) * 16 + nt * 4 + 0];                              \
        uint32_t bh1 = wf[(ki) * 16 + nt * 4 + 1];                              \
        uint32_t bl0 = wf[(ki) * 16 + nt * 4 + 2];                              \
        uint32_t bl1 = wf[(ki) * 16 + nt * 4 + 3];                              \
        mma_bf16(c[0][nt], ah,     bh0, bh1);                                   \
        mma_bf16(c[1][nt], ah + 4, bh0, bh1);                                   \
        mma_bf16(c[0][nt], ah,     bl0, bl1);                                   \
        mma_bf16(c[1][nt], ah + 4, bl0, bl1);                                   \
        mma_bf16(c[0][nt], al,     bh0, bh1);                                   \
        mma_bf16(c[1][nt], al + 4, bh0, bh1);                                   \
    }                                                                           \
}

__global__ __launch_bounds__(256, 1) void lstm_rec(
    const float* __restrict__ Wf, const float* __restrict__ Wb,
    float* __restrict__ outbuf, int st_t, int st_b)
{
    extern __shared__ char smr[];
    uint32_t sbase = smem_u32(smr);

    int dir = blockIdx.x & 1;
    int cb = blockIdx.x >> 1;
    int u0 = cb * 8;
    const float* W = dir ? Wb : Wf;
    const float* xg = dir ? g_xg1 : g_xg0;
    int tid = threadIdx.x;
    int wid = tid >> 5, l = tid & 31;
    int gid = l >> 2, tig = l & 3;

    // ---- split this CTA's 32 W_hh rows into bf16 hi/lo SMEM planes (once) ----
    {
        int c = tid >> 3, kq = tid & 7;
        const float* wrow = W + (size_t)((c >> 3) * Hz + u0 + (c & 7)) * Hz;
        unsigned short* whi = (unsigned short*)(smr + RSM_WHI);
        unsigned short* wlo = (unsigned short*)(smr + RSM_WLO);
#pragma unroll 4
        for (int p = 0; p < 16; p++) {
            int k = p * 32 + kq * 4;
            float4 v = *(const float4*)&wrow[k];
            float vv[4] = {v.x, v.y, v.z, v.w};
#pragma unroll
            for (int j = 0; j < 4; j++) {
                __nv_bfloat16 hb = __float2bfloat16(vv[j]);
                whi[c * 520 + k + j] = __bfloat16_as_ushort(hb);
                wlo[c * 520 + k + j] = __bfloat16_as_ushort(
                    __float2bfloat16(vv[j] - __bfloat162float(hb)));
            }
        }
    }

    // ---- zero h parity-0 planes (this CTA's 1/64 slice), publish #1 ----
    g_hhi[dir][0][cb * 256 + tid] = 0;
    g_hlo[dir][0][cb * 256 + tid] = 0;
    float creg = 0.f;
    __syncthreads();
    if (tid == 0) {
        __threadfence();
        asm volatile("red.global.gpu.add.u32 [%0], 1;" :: "l"(&g_flag[dir][cb]) : "memory");
    }

    // ldmatrix bases (warp k-offset = wid*64 k = wid*128 bytes)
    uint32_t abase = sbase + RSM_AHI + (uint32_t)(l & 15) * RST
                   + (uint32_t)((l >> 4) * 16) + (uint32_t)wid * 128;
    uint32_t bbase = sbase + RSM_WHI + (uint32_t)(l & 7) * RST
                   + (uint32_t)(((l >> 3) & 1) * 16) + (uint32_t)wid * 128;
    float* ps = (float*)(smr + RSM_PS);
    int bb = tid >> 3, uul = tid & 7;          // this thread's (batch, unit)

    // ---- hoist W fragments into registers (step-invariant) ----
    uint32_t wf[64];
#pragma unroll
    for (int ki = 0; ki < 4; ki++)
#pragma unroll
        for (int nt = 0; nt < 4; nt++) {
            LDSM2(wf[ki * 16 + nt * 4 + 0], wf[ki * 16 + nt * 4 + 1],
                  bbase + nt * 8 * RST + ki * 32);
            LDSM2(wf[ki * 16 + nt * 4 + 2], wf[ki * 16 + nt * 4 + 3],
                  bbase + 33280 + nt * 8 * RST + ki * 32);
        }

    // prefetch xg for step 0
    float xv[4];
    {
        int t0v = dir ? (Tz - 1) : 0;
        const float* xr = xg + (size_t)t0v * Bz * Gz + (size_t)bb * Gz + u0 + uul;
        xv[0] = xr[0 * Hz]; xv[1] = xr[1 * Hz]; xv[2] = xr[2 * Hz]; xv[3] = xr[3 * Hz];
    }

    const unsigned* myflags = &g_flag[dir][wid * 8];

    for (int s = 0; s < Tz; s++) {
        int rb = s & 1;
        int wb = rb ^ 1;
        int t = dir ? (Tz - 1 - s) : s;

        // ---- wait for this warp's 8 producer CTAs to publish h(s) ----
        {
            unsigned tgt = (unsigned)(s + 1);
            if (l < 8) {
                const unsigned* f = myflags + l;
                unsigned v;
                do {
                    asm volatile("ld.acquire.gpu.u32 %0, [%1];" : "=r"(v) : "l"(f) : "memory");
                } while (v < tgt);
            }
            __syncwarp();
        }

        // ---- per-warp pipelined staging: 4 commit groups (one per ki) ----
        {
            const char* hhi = (const char*)g_hhi[dir][rb];
            const char* hlo = (const char*)g_hlo[dir][rb];
            int r0 = l >> 1;
#pragma unroll
            for (int g = 0; g < 4; g++) {
                int co = wid * 128 + g * 32 + (l & 1) * 16;
                CP16(sbase + RSM_AHI + r0 * RST + co,        hhi + r0 * 1024 + co);
                CP16(sbase + RSM_AHI + (r0 + 16) * RST + co, hhi + (r0 + 16) * 1024 + co);
                CP16(sbase + RSM_ALO + r0 * RST + co,        hlo + r0 * 1024 + co);
                CP16(sbase + RSM_ALO + (r0 + 16) * RST + co, hlo + (r0 + 16) * 1024 + co);
                CPCOMMIT();
            }
        }

        // ---- partial gates: 32b x 32cols over this warp's k64, 3-mma split ----
        float c[2][4][4];
#pragma unroll
        for (int mt = 0; mt < 2; mt++)
#pragma unroll
            for (int nt = 0; nt < 4; nt++)
#pragma unroll
                for (int q = 0; q < 4; q++) c[mt][nt][q] = 0.f;

        REC_KI(0, 3)
        REC_KI(1, 2)
        REC_KI(2, 1)
        REC_KI(3, 0)

        // ---- scatter partials to ps[wid][32][40] ----
        {
            float* pw = ps + wid * (32 * 40);
#pragma unroll
            for (int nt = 0; nt < 4; nt++) {
                int col = nt * 8 + 2 * tig;
                float2 v;
                v.x = c[0][nt][0]; v.y = c[0][nt][1];
                *(float2*)&pw[(gid)      * 40 + col] = v;
                v.x = c[0][nt][2]; v.y = c[0][nt][3];
                *(float2*)&pw[(gid + 8)  * 40 + col] = v;
                v.x = c[1][nt][0]; v.y = c[1][nt][1];
                *(float2*)&pw[(gid + 16) * 40 + col] = v;
                v.x = c[1][nt][2]; v.y = c[1][nt][3];
                *(float2*)&pw[(gid + 24) * 40 + col] = v;
            }
        }
        __syncthreads();

        // ---- reduce 8 partials + gates + state update (1 (b,u) per thread) ----
        float hn;
        {
            float gv4[4];
#pragma unroll
            for (int g = 0; g < 4; g++) {
                int base = bb * 40 + g * 8 + uul;
                float acc = xv[g];
#pragma unroll
                for (int w = 0; w < 8; w++) acc += ps[base + w * 1280];
                gv4[g] = acc;
            }
            float iv = sigf(gv4[0]), fv = sigf(gv4[1]);
            float gg = tanhf_(gv4[2]), ov = sigf(gv4[3]);
            float cn = fv * creg + iv * gg;
            hn = ov * tanhf_(cn);
            creg = cn;
            __nv_bfloat16 hb = __float2bfloat16(hn);
            g_hhi[dir][wb][bb * 512 + u0 + uul] = __bfloat16_as_ushort(hb);
            g_hlo[dir][wb][bb * 512 + u0 + uul] = __bfloat16_as_ushort(
                __float2bfloat16(hn - __bfloat162float(hb)));
        }

        // ---- publish h(s+1): fence + per-CTA flag bump (distinct address) ----
        __syncthreads();
        if (tid == 0) {
            __threadfence();
            asm volatile("red.global.gpu.add.u32 [%0], 1;" :: "l"(&g_flag[dir][cb]) : "memory");
        }
        // off-critical-path: output store + next-step xg prefetch
        outbuf[(size_t)t * st_t + (size_t)bb * st_b + dir * Hz + u0 + uul] = hn;
        if (s + 1 < Tz) {
            int tn = dir ? (Tz - 2 - s) : (s + 1);
            const float* xr = xg + (size_t)tn * Bz * Gz + (size_t)bb * Gz + u0 + uul;
            xv[0] = xr[0 * Hz]; xv[1] = xr[1 * Hz];
            xv[2] = xr[2 * Hz]; xv[3] = xr[3 * Hz];
        }
    }

    g_cbuf[dir][bb * Hz + u0 + uul] = creg;
}

// -------- copy final h/c into h_n / c_n sections of d_out --------
__global__ void copy_state(float* __restrict__ dout, int layer) {
    int idx = blockIdx.x * 256 + threadIdx.x;   // 0..32767
    int d = idx >> 14;
    int r = idx & 16383;           // r = b*512 + u
    const size_t OUT = (size_t)Bz * Tz * 2 * Hz;
    float hv = __bfloat162float(__ushort_as_bfloat16(g_hhi[d][0][r]))
             + __bfloat162float(__ushort_as_bfloat16(g_hlo[d][0][r]));
    dout[OUT + (size_t)(2 * layer + d) * (Bz * Hz) + r] = hv;
    dout[OUT + 4 * (size_t)(Bz * Hz) + (size_t)(2 * layer + d) * (Bz * Hz) + r] = g_cbuf[d][r];
}

extern "C" void kernel_launch(void* const* d_in, const int* in_sizes, int n_in,
                              void* d_out, int out_size)
{
    const float* x        = (const float*)d_in[0];
    const float* w_ih_l0  = (const float*)d_in[1];
    const float* w_hh_l0  = (const float*)d_in[2];
    const float* b_ih_l0  = (const float*)d_in[3];
    const float* b_hh_l0  = (const float*)d_in[4];
    const float* w_ih_l0r = (const float*)d_in[5];
    const float* w_hh_l0r = (const float*)d_in[6];
    const float* b_ih_l0r = (const float*)d_in[7];
    const float* b_hh_l0r = (const float*)d_in[8];
    const float* w_ih_l1  = (const float*)d_in[9];
    const float* w_hh_l1  = (const float*)d_in[10];
    const float* b_ih_l1  = (const float*)d_in[11];
    const float* b_hh_l1  = (const float*)d_in[12];
    const float* w_ih_l1r = (const float*)d_in[13];
    const float* w_hh_l1r = (const float*)d_in[14];
    const float* b_ih_l1r = (const float*)d_in[15];
    const float* b_hh_l1r = (const float*)d_in[16];
    float* out = (float*)d_out;

    void* p;
    float *xt, *y0, *xg0, *xg1;
    cudaGetSymbolAddress(&p, g_xt);   xt  = (float*)p;
    cudaGetSymbolAddress(&p, g_y0);   y0  = (float*)p;
    cudaGetSymbolAddress(&p, g_xg0);  xg0 = (float*)p;
    cudaGetSymbolAddress(&p, g_xg1);  xg1 = (float*)p;

    cudaFuncSetAttribute(lstm_rec, cudaFuncAttributeMaxDynamicSharedMemorySize,
                         REC_SMEM_BYTES);

    // x [B,I,T] -> xt [T,B,I]
    transpose_x<<<dim3(Tz / 32, Iz / 32, Bz), dim3(32, 8)>>>(x);

    dim3 gg(Gz / 128, TB / 128);   // (16, 128)

    // ---- layer 0 ----
    gemm_xg_mma<<<gg, 256>>>(xt, w_ih_l0,  b_ih_l0,  b_hh_l0,  xg0, Iz);
    gemm_xg_mma<<<gg, 256>>>(xt, w_ih_l0r, b_ih_l0r, b_hh_l0r, xg1, Iz);
    reset_flags<<<1, 128>>>();
    lstm_rec<<<128, 256, REC_SMEM_BYTES>>>(w_hh_l0, w_hh_l0r, y0,
                                           Bz * 2 * Hz, 2 * Hz);
    copy_state<<<128, 256>>>(out, 0);

    // ---- layer 1 ----
    gemm_xg_mma<<<gg, 256>>>(y0, w_ih_l1,  b_ih_l1,  b_hh_l1,  xg0, 2 * Hz);
    gemm_xg_mma<<<gg, 256>>>(y0, w_ih_l1r, b_ih_l1r, b_hh_l1r, xg1, 2 * Hz);
    reset_flags<<<1, 128>>>();
    lstm_rec<<<128, 256, REC_SMEM_BYTES>>>(w_hh_l1, w_hh_l1r, out,
                                           2 * Hz, Tz * 2 * Hz);
    copy_state<<<128, 256>>>(out, 1);
}

// round 11
// speedup vs baseline: 3.9250x; 1.1713x over previous
#include <cuda_runtime.h>
#include <cuda_bf16.h>
#include <cstdint>

#define Tz 512
#define Bz 32
#define Iz 256
#define Hz 512
#define Gz 2048          // 4*H
#define TB (Tz*Bz)       // 16384

// -------- scratch (device globals; no runtime allocation) --------
__device__ float g_xt[(size_t)TB * Iz];        // x transposed to [T,B,I]
__device__ float g_xg0[(size_t)TB * Gz];       // fwd-dir input-gate projections
__device__ float g_xg1[(size_t)TB * Gz];       // bwd-dir input-gate projections
__device__ float g_y0[(size_t)TB * 2 * Hz];    // layer-0 output [T,B,2H]
__device__ unsigned g_hpk[2][2][Bz * Hz];      // [dir][parity][b*512+u] (bf16hi<<16)|bf16lo
__device__ float g_cbuf[2][Bz * Hz];           // [dir][b*H+u]
__device__ unsigned g_flag[2][64];             // per-CTA publish counters

__device__ __forceinline__ float sigf(float x) { return 1.f / (1.f + __expf(-x)); }
__device__ __forceinline__ float tanhf_(float x) { return 2.f / (1.f + __expf(-2.f * x)) - 1.f; }

__device__ __forceinline__ uint32_t f2tf32(float f) {
    uint32_t r;
    asm("cvt.rna.tf32.f32 %0, %1;" : "=r"(r) : "f"(f));
    return r;
}

__device__ __forceinline__ uint32_t smem_u32(const void* p) {
    uint32_t a;
    asm("{ .reg .u64 t; cvta.to.shared.u64 t, %1; cvt.u32.u64 %0, t; }" : "=r"(a) : "l"(p));
    return a;
}

// mma.sync tf32 m16n8k8 (input GEMMs)
__device__ __forceinline__ void mma_tf32(float* c, const uint32_t* a,
                                         uint32_t b0, uint32_t b1) {
    asm volatile(
        "mma.sync.aligned.m16n8k8.row.col.f32.tf32.tf32.f32 "
        "{%0,%1,%2,%3}, {%4,%5,%6,%7}, {%8,%9}, {%0,%1,%2,%3};"
        : "+f"(c[0]), "+f"(c[1]), "+f"(c[2]), "+f"(c[3])
        : "r"(a[0]), "r"(a[1]), "r"(a[2]), "r"(a[3]), "r"(b0), "r"(b1));
}

// mma.sync bf16 m16n8k16 (recurrence)
__device__ __forceinline__ void mma_bf16(float* c, const uint32_t* a,
                                         uint32_t b0, uint32_t b1) {
    asm volatile(
        "mma.sync.aligned.m16n8k16.row.col.f32.bf16.bf16.f32 "
        "{%0,%1,%2,%3}, {%4,%5,%6,%7}, {%8,%9}, {%0,%1,%2,%3};"
        : "+f"(c[0]), "+f"(c[1]), "+f"(c[2]), "+f"(c[3])
        : "r"(a[0]), "r"(a[1]), "r"(a[2]), "r"(a[3]), "r"(b0), "r"(b1));
}

#define LDSM2(d0, d1, a)                                                        \
    asm volatile("ldmatrix.sync.aligned.m8n8.x2.shared.b16 {%0,%1}, [%2];"      \
                 : "=r"(d0), "=r"(d1) : "r"(a))

// -------- transpose x [B,I,T] -> xt [T,B,I] --------
__global__ void transpose_x(const float* __restrict__ x) {
    __shared__ float tile[32][33];
    int b = blockIdx.z, i0 = blockIdx.y * 32, t0 = blockIdx.x * 32;
    int tx = threadIdx.x, ty = threadIdx.y;
#pragma unroll
    for (int r = ty; r < 32; r += 8)
        tile[r][tx] = x[(size_t)b * Iz * Tz + (size_t)(i0 + r) * Tz + t0 + tx];
    __syncthreads();
#pragma unroll
    for (int r = ty; r < 32; r += 8)
        g_xt[(size_t)(t0 + r) * Bz * Iz + (size_t)b * Iz + i0 + tx] = tile[tx][r];
}

// ======== tf32 mma.sync GEMM: C[M,Gz] = A[M,K] @ W[Gz,K]^T + bi + bh ========
__global__ __launch_bounds__(256) void gemm_xg_mma(
    const float* __restrict__ A, const float* __restrict__ W,
    const float* __restrict__ bi, const float* __restrict__ bh,
    float* __restrict__ C, int K)
{
    __shared__ uint32_t As[128 * 36];
    __shared__ uint32_t Bs[128 * 36];

    int tid = threadIdx.x;
    int wid = tid >> 5, lane = tid & 31;
    int gid = lane >> 2, tig = lane & 3;
    int n0 = blockIdx.x * 128, m0 = blockIdx.y * 128;
    int mwarp = (wid >> 1) * 32;
    int nwarp = (wid & 1) * 64;
    int lrow = tid >> 3, lq = tid & 7;

    float c[2][8][4];
#pragma unroll
    for (int mt = 0; mt < 2; mt++)
#pragma unroll
        for (int nt = 0; nt < 8; nt++)
#pragma unroll
            for (int q = 0; q < 4; q++) c[mt][nt][q] = 0.f;

    float4 pa[4], pb[4];
#pragma unroll
    for (int j = 0; j < 4; j++) {
        pa[j] = *(const float4*)&A[(size_t)(m0 + lrow + j * 32) * K + lq * 4];
        pb[j] = *(const float4*)&W[(size_t)(n0 + lrow + j * 32) * K + lq * 4];
    }

    for (int k0 = 0; k0 < K; k0 += 32) {
#pragma unroll
        for (int j = 0; j < 4; j++) {
            uint4 ta, tb;
            ta.x = f2tf32(pa[j].x); ta.y = f2tf32(pa[j].y);
            ta.z = f2tf32(pa[j].z); ta.w = f2tf32(pa[j].w);
            tb.x = f2tf32(pb[j].x); tb.y = f2tf32(pb[j].y);
            tb.z = f2tf32(pb[j].z); tb.w = f2tf32(pb[j].w);
            *(uint4*)&As[(lrow + j * 32) * 36 + lq * 4] = ta;
            *(uint4*)&Bs[(lrow + j * 32) * 36 + lq * 4] = tb;
        }
        __syncthreads();

        if (k0 + 32 < K) {
#pragma unroll
            for (int j = 0; j < 4; j++) {
                pa[j] = *(const float4*)&A[(size_t)(m0 + lrow + j * 32) * K + k0 + 32 + lq * 4];
                pb[j] = *(const float4*)&W[(size_t)(n0 + lrow + j * 32) * K + k0 + 32 + lq * 4];
            }
        }

#pragma unroll
        for (int kk = 0; kk < 32; kk += 8) {
            uint32_t a[2][4];
#pragma unroll
            for (int mt = 0; mt < 2; mt++) {
                int mrow = mwarp + mt * 16;
                a[mt][0] = As[(mrow + gid)     * 36 + kk + tig];
                a[mt][1] = As[(mrow + gid + 8) * 36 + kk + tig];
                a[mt][2] = As[(mrow + gid)     * 36 + kk + tig + 4];
                a[mt][3] = As[(mrow + gid + 8) * 36 + kk + tig + 4];
            }
#pragma unroll
            for (int nt = 0; nt < 8; nt++) {
                uint32_t b0 = Bs[(nwarp + nt * 8 + gid) * 36 + kk + tig];
                uint32_t b1 = Bs[(nwarp + nt * 8 + gid) * 36 + kk + tig + 4];
                mma_tf32(c[0][nt], a[0], b0, b1);
                mma_tf32(c[1][nt], a[1], b0, b1);
            }
        }
        __syncthreads();
    }

#pragma unroll
    for (int mt = 0; mt < 2; mt++) {
        int m = m0 + mwarp + mt * 16 + gid;
#pragma unroll
        for (int nt = 0; nt < 8; nt++) {
            int n = n0 + nwarp + nt * 8 + 2 * tig;
            float bs0 = bi[n] + bh[n];
            float bs1 = bi[n + 1] + bh[n + 1];
            float2 o0 = {c[mt][nt][0] + bs0, c[mt][nt][1] + bs1};
            float2 o1 = {c[mt][nt][2] + bs0, c[mt][nt][3] + bs1};
            *(float2*)&C[(size_t)m * Gz + n] = o0;
            *(float2*)&C[(size_t)(m + 8) * Gz + n] = o1;
        }
    }
}

__global__ void reset_flags() {
    if (threadIdx.x < 128) ((unsigned*)g_flag)[threadIdx.x] = 0;
}

// ======== persistent recurrence — K-split bf16, direct-L2 fragment loads ========
// h lives in global as packed (bf16hi<<16)|bf16lo words; each warp LDG.64s its
// mma A-fragments straight from L2 (no SMEM staging), splits hi/lo with PRMT.
// W fragments hoisted to registers at init; partials reduced across 8 warps.
#define RST 1040                      // W smem row stride bytes (520 bf16)
#define RSM_WHI 0                     // [32 c][520]
#define RSM_WLO 33280
#define RSM_PS  66560                 // float[8][32][40]
#define REC_SMEM_BYTES (66560 + 8 * 32 * 40 * 4)

__global__ __launch_bounds__(256, 1) void lstm_rec(
    const float* __restrict__ Wf, const float* __restrict__ Wb,
    float* __restrict__ outbuf, int st_t, int st_b)
{
    extern __shared__ char smr[];
    uint32_t sbase = smem_u32(smr);

    int dir = blockIdx.x & 1;
    int cb = blockIdx.x >> 1;
    int u0 = cb * 8;
    const float* W = dir ? Wb : Wf;
    const float* xg = dir ? g_xg1 : g_xg0;
    int tid = threadIdx.x;
    int wid = tid >> 5, l = tid & 31;
    int gid = l >> 2, tig = l & 3;

    // ---- split this CTA's 32 W_hh rows into bf16 hi/lo SMEM planes (once) ----
    {
        int c = tid >> 3, kq = tid & 7;
        const float* wrow = W + (size_t)((c >> 3) * Hz + u0 + (c & 7)) * Hz;
        unsigned short* whi = (unsigned short*)(smr + RSM_WHI);
        unsigned short* wlo = (unsigned short*)(smr + RSM_WLO);
#pragma unroll 4
        for (int p = 0; p < 16; p++) {
            int k = p * 32 + kq * 4;
            float4 v = *(const float4*)&wrow[k];
            float vv[4] = {v.x, v.y, v.z, v.w};
#pragma unroll
            for (int j = 0; j < 4; j++) {
                __nv_bfloat16 hb = __float2bfloat16(vv[j]);
                whi[c * 520 + k + j] = __bfloat16_as_ushort(hb);
                wlo[c * 520 + k + j] = __bfloat16_as_ushort(
                    __float2bfloat16(vv[j] - __bfloat162float(hb)));
            }
        }
    }

    // ---- zero h parity-0 (this CTA's 1/64 slice), publish #1 ----
    g_hpk[dir][0][cb * 256 + tid] = 0u;
    float creg = 0.f;
    __syncthreads();
    if (tid == 0)
        asm volatile("red.release.gpu.global.add.u32 [%0], 1;"
                     :: "l"(&g_flag[dir][cb]) : "memory");

    // W-fragment ldmatrix base
    uint32_t bbase = sbase + RSM_WHI + (uint32_t)(l & 7) * RST
                   + (uint32_t)(((l >> 3) & 1) * 16) + (uint32_t)wid * 128;
    float* ps = (float*)(smr + RSM_PS);
    int bb = tid >> 3, uul = tid & 7;          // this thread's (batch, unit)

    // ---- hoist W fragments into registers (step-invariant) ----
    uint32_t wf[64];
#pragma unroll
    for (int ki = 0; ki < 4; ki++)
#pragma unroll
        for (int nt = 0; nt < 4; nt++) {
            LDSM2(wf[ki * 16 + nt * 4 + 0], wf[ki * 16 + nt * 4 + 1],
                  bbase + nt * 8 * RST + ki * 32);
            LDSM2(wf[ki * 16 + nt * 4 + 2], wf[ki * 16 + nt * 4 + 3],
                  bbase + 33280 + nt * 8 * RST + ki * 32);
        }

    // prefetch xg for step 0
    float xv[4];
    {
        int t0v = dir ? (Tz - 1) : 0;
        const float* xr = xg + (size_t)t0v * Bz * Gz + (size_t)bb * Gz + u0 + uul;
        xv[0] = xr[0 * Hz]; xv[1] = xr[1 * Hz]; xv[2] = xr[2 * Hz]; xv[3] = xr[3 * Hz];
    }

    const unsigned* myflag = &g_flag[dir][wid * 8 + (l & 7)];
    int kcb = wid * 64 + 2 * tig;              // this lane's base k column

    for (int s = 0; s < Tz; s++) {
        int rb = s & 1;
        int wb = rb ^ 1;
        int t = dir ? (Tz - 1 - s) : s;

        // ---- all lanes acquire-poll their producer flag (8 producers/warp) ----
        {
            unsigned tgt = (unsigned)(s + 1), v;
            do {
                asm volatile("ld.acquire.gpu.u32 %0, [%1];" : "=r"(v) : "l"(myflag) : "memory");
            } while (v < tgt);
        }

        // ---- direct-L2 A-fragment loads: 32x LDG.64 per warp (packed hi|lo) ----
        const unsigned* hp = g_hpk[dir][rb];
        uint2 wv[4][8];
#pragma unroll
        for (int ki = 0; ki < 4; ki++) {
            int kc = kcb + ki * 16;
#pragma unroll
            for (int mt = 0; mt < 2; mt++) {
                int r = mt * 16 + gid;
                wv[ki][mt * 4 + 0] = __ldcg((const uint2*)&hp[r * 512 + kc]);
                wv[ki][mt * 4 + 1] = __ldcg((const uint2*)&hp[(r + 8) * 512 + kc]);
                wv[ki][mt * 4 + 2] = __ldcg((const uint2*)&hp[r * 512 + kc + 8]);
                wv[ki][mt * 4 + 3] = __ldcg((const uint2*)&hp[(r + 8) * 512 + kc + 8]);
            }
        }

        // ---- partial gates: 32b x 32cols over this warp's k64, 3-mma split ----
        float c[2][4][4];
#pragma unroll
        for (int mt = 0; mt < 2; mt++)
#pragma unroll
            for (int nt = 0; nt < 4; nt++)
#pragma unroll
                for (int q = 0; q < 4; q++) c[mt][nt][q] = 0.f;

#pragma unroll
        for (int ki = 0; ki < 4; ki++) {
            uint32_t ah[8], al[8];
#pragma unroll
            for (int j = 0; j < 8; j++) {
                ah[j] = __byte_perm(wv[ki][j].x, wv[ki][j].y, 0x7632);
                al[j] = __byte_perm(wv[ki][j].x, wv[ki][j].y, 0x5410);
            }
#pragma unroll
            for (int nt = 0; nt < 4; nt++) {
                uint32_t bh0 = wf[ki * 16 + nt * 4 + 0];
                uint32_t bh1 = wf[ki * 16 + nt * 4 + 1];
                uint32_t bl0 = wf[ki * 16 + nt * 4 + 2];
                uint32_t bl1 = wf[ki * 16 + nt * 4 + 3];
                mma_bf16(c[0][nt], ah,     bh0, bh1);
                mma_bf16(c[1][nt], ah + 4, bh0, bh1);
                mma_bf16(c[0][nt], ah,     bl0, bl1);
                mma_bf16(c[1][nt], ah + 4, bl0, bl1);
                mma_bf16(c[0][nt], al,     bh0, bh1);
                mma_bf16(c[1][nt], al + 4, bh0, bh1);
            }
        }

        // ---- scatter partials to ps[wid][32][40] ----
        {
            float* pw = ps + wid * (32 * 40);
#pragma unroll
            for (int nt = 0; nt < 4; nt++) {
                int col = nt * 8 + 2 * tig;
                float2 v;
                v.x = c[0][nt][0]; v.y = c[0][nt][1];
                *(float2*)&pw[(gid)      * 40 + col] = v;
                v.x = c[0][nt][2]; v.y = c[0][nt][3];
                *(float2*)&pw[(gid + 8)  * 40 + col] = v;
                v.x = c[1][nt][0]; v.y = c[1][nt][1];
                *(float2*)&pw[(gid + 16) * 40 + col] = v;
                v.x = c[1][nt][2]; v.y = c[1][nt][3];
                *(float2*)&pw[(gid + 24) * 40 + col] = v;
            }
        }
        __syncthreads();

        // ---- reduce 8 partials + gates + state update (1 (b,u) per thread) ----
        float hn;
        {
            float gv4[4];
#pragma unroll
            for (int g = 0; g < 4; g++) {
                int base = bb * 40 + g * 8 + uul;
                float acc = xv[g];
#pragma unroll
                for (int w = 0; w < 8; w++) acc += ps[base + w * 1280];
                gv4[g] = acc;
            }
            float iv = sigf(gv4[0]), fv = sigf(gv4[1]);
            float gg = tanhf_(gv4[2]), ov = sigf(gv4[3]);
            float cn = fv * creg + iv * gg;
            hn = ov * tanhf_(cn);
            creg = cn;
            __nv_bfloat16 hb = __float2bfloat16(hn);
            unsigned hi = __bfloat16_as_ushort(hb);
            unsigned lo = __bfloat16_as_ushort(
                __float2bfloat16(hn - __bfloat162float(hb)));
            g_hpk[dir][wb][bb * 512 + u0 + uul] = (hi << 16) | lo;
        }

        // ---- publish h(s+1): release-atomic per-CTA flag bump ----
        __syncthreads();
        if (tid == 0)
            asm volatile("red.release.gpu.global.add.u32 [%0], 1;"
                         :: "l"(&g_flag[dir][cb]) : "memory");
        // off-critical-path: output store + next-step xg prefetch
        outbuf[(size_t)t * st_t + (size_t)bb * st_b + dir * Hz + u0 + uul] = hn;
        if (s + 1 < Tz) {
            int tn = dir ? (Tz - 2 - s) : (s + 1);
            const float* xr = xg + (size_t)tn * Bz * Gz + (size_t)bb * Gz + u0 + uul;
            xv[0] = xr[0 * Hz]; xv[1] = xr[1 * Hz];
            xv[2] = xr[2 * Hz]; xv[3] = xr[3 * Hz];
        }
    }

    g_cbuf[dir][bb * Hz + u0 + uul] = creg;
}

// -------- copy final h/c into h_n / c_n sections of d_out --------
__global__ void copy_state(float* __restrict__ dout, int layer) {
    int idx = blockIdx.x * 256 + threadIdx.x;   // 0..32767
    int d = idx >> 14;
    int r = idx & 16383;           // r = b*512 + u
    const size_t OUT = (size_t)Bz * Tz * 2 * Hz;
    unsigned w = g_hpk[d][0][r];
    float hv = __bfloat162float(__ushort_as_bfloat16((unsigned short)(w >> 16)))
             + __bfloat162float(__ushort_as_bfloat16((unsigned short)(w & 0xFFFFu)));
    dout[OUT + (size_t)(2 * layer + d) * (Bz * Hz) + r] = hv;
    dout[OUT + 4 * (size_t)(Bz * Hz) + (size_t)(2 * layer + d) * (Bz * Hz) + r] = g_cbuf[d][r];
}

extern "C" void kernel_launch(void* const* d_in, const int* in_sizes, int n_in,
                              void* d_out, int out_size)
{
    const float* x        = (const float*)d_in[0];
    const float* w_ih_l0  = (const float*)d_in[1];
    const float* w_hh_l0  = (const float*)d_in[2];
    const float* b_ih_l0  = (const float*)d_in[3];
    const float* b_hh_l0  = (const float*)d_in[4];
    const float* w_ih_l0r = (const float*)d_in[5];
    const float* w_hh_l0r = (const float*)d_in[6];
    const float* b_ih_l0r = (const float*)d_in[7];
    const float* b_hh_l0r = (const float*)d_in[8];
    const float* w_ih_l1  = (const float*)d_in[9];
    const float* w_hh_l1  = (const float*)d_in[10];
    const float* b_ih_l1  = (const float*)d_in[11];
    const float* b_hh_l1  = (const float*)d_in[12];
    const float* w_ih_l1r = (const float*)d_in[13];
    const float* w_hh_l1r = (const float*)d_in[14];
    const float* b_ih_l1r = (const float*)d_in[15];
    const float* b_hh_l1r = (const float*)d_in[16];
    float* out = (float*)d_out;

    void* p;
    float *xt, *y0, *xg0, *xg1;
    cudaGetSymbolAddress(&p, g_xt);   xt  = (float*)p;
    cudaGetSymbolAddress(&p, g_y0);   y0  = (float*)p;
    cudaGetSymbolAddress(&p, g_xg0);  xg0 = (float*)p;
    cudaGetSymbolAddress(&p, g_xg1);  xg1 = (float*)p;

    cudaFuncSetAttribute(lstm_rec, cudaFuncAttributeMaxDynamicSharedMemorySize,
                         REC_SMEM_BYTES);

    // x [B,I,T] -> xt [T,B,I]
    transpose_x<<<dim3(Tz / 32, Iz / 32, Bz), dim3(32, 8)>>>(x);

    dim3 gg(Gz / 128, TB / 128);   // (16, 128)

    // ---- layer 0 ----
    gemm_xg_mma<<<gg, 256>>>(xt, w_ih_l0,  b_ih_l0,  b_hh_l0,  xg0, Iz);
    gemm_xg_mma<<<gg, 256>>>(xt, w_ih_l0r, b_ih_l0r, b_hh_l0r, xg1, Iz);
    reset_flags<<<1, 128>>>();
    lstm_rec<<<128, 256, REC_SMEM_BYTES>>>(w_hh_l0, w_hh_l0r, y0,
                                           Bz * 2 * Hz, 2 * Hz);
    copy_state<<<128, 256>>>(out, 0);

    // ---- layer 1 ----
    gemm_xg_mma<<<gg, 256>>>(y0, w_ih_l1,  b_ih_l1,  b_hh_l1,  xg0, 2 * Hz);
    gemm_xg_mma<<<gg, 256>>>(y0, w_ih_l1r, b_ih_l1r, b_hh_l1r, xg1, 2 * Hz);
    reset_flags<<<1, 128>>>();
    lstm_rec<<<128, 256, REC_SMEM_BYTES>>>(w_hh_l1, w_hh_l1r, out,
                                           2 * Hz, Tz * 2 * Hz);
    copy_state<<<128, 256>>>(out, 1);
}